// round 7
// baseline (speedup 1.0000x reference)
#include <cuda_runtime.h>
#include <cuda_fp16.h>
#include <math.h>

#define NNODES 50000
#define NEDGES 800000
#define INF    128
#define HID    64
#define HEADS  4
#define C1     256   // HEADS*HID
#define NEG    0.2f

// ---------------- scratch (device globals; no runtime allocation) ----------
__device__ __half g_h1h [NNODES * C1];  // layer1 pre-attention features (fp16)
__device__ __half g_h1eh[NNODES * C1];  // layer1 output (post bias+ELU), fp16
__device__ float  g_as1[NNODES * HEADS];
__device__ float  g_ad1[NNODES * HEADS];
__device__ __half g_h2h[NNODES * HID];  // layer2 pre-attention features (fp16)
__device__ float  g_as2[NNODES];
__device__ float  g_ad2[NNODES];
__device__ int    g_deg   [NNODES];
__device__ int    g_rowptr[NNODES + 1];
__device__ int    g_cursor[NNODES];
__device__ int    g_col   [NEDGES];
__device__ int    g_bsum  [64];

typedef unsigned long long ull;

__device__ __forceinline__ ull ffma2(ull a, ull b, ull c) {
    ull d;
    asm("fma.rn.f32x2 %0, %1, %2, %3;" : "=l"(d) : "l"(a), "l"(b), "l"(c));
    return d;
}
__device__ __forceinline__ ull pack2(float lo, float hi) {
    ull d;
    asm("mov.b64 %0, {%1, %2};" : "=l"(d) : "f"(lo), "f"(hi));
    return d;
}
__device__ __forceinline__ float2 unpack2(ull v) {
    float2 r;
    asm("mov.b64 {%0, %1}, %2;" : "=f"(r.x), "=f"(r.y) : "l"(v));
    return r;
}
__device__ __forceinline__ float lrelu(float v) { return v > 0.f ? v : NEG * v; }

// ---------------- CSR construction ------------------------------------------
__global__ void k_hist(const int* __restrict__ dst) {
    int i = blockIdx.x * blockDim.x + threadIdx.x;
    if (i < NEDGES) atomicAdd(&g_deg[dst[i]], 1);
}

__global__ void k_scan1() {
    __shared__ int sh[1024];
    int tid = threadIdx.x;
    int i = blockIdx.x * 1024 + tid;
    int v = (i < NNODES) ? g_deg[i] : 0;
    sh[tid] = v;
    __syncthreads();
    for (int s = 1; s < 1024; s <<= 1) {
        int t = (tid >= s) ? sh[tid - s] : 0;
        __syncthreads();
        sh[tid] += t;
        __syncthreads();
    }
    if (i < NNODES) g_rowptr[i] = sh[tid] - v;
    if (tid == 1023) g_bsum[blockIdx.x] = sh[1023];
}

// apply per-block offset, init cursor, zero g_deg for next replay
__global__ void k_scan23() {
    __shared__ int soff;
    int tid = threadIdx.x;
    int bid = blockIdx.x;
    if (tid < 32) {
        int v = 0;
        if (tid < bid && tid < 49) v += g_bsum[tid];
        int t2 = tid + 32;
        if (t2 < bid && t2 < 49) v += g_bsum[t2];
#pragma unroll
        for (int s = 16; s >= 1; s >>= 1) v += __shfl_xor_sync(0xffffffffu, v, s);
        if (tid == 0) soff = v;
    }
    __syncthreads();
    int i = bid * 1024 + tid;
    if (i < NNODES) {
        int r = g_rowptr[i] + soff;
        g_rowptr[i] = r;
        g_cursor[i] = r;
        g_deg[i] = 0;
    }
    if (i == 0) g_rowptr[NNODES] = NEDGES;
}

__global__ void k_scatter(const int* __restrict__ src, const int* __restrict__ dst) {
    int i = blockIdx.x * blockDim.x + threadIdx.x;
    if (i < NEDGES) {
        int p = atomicAdd(&g_cursor[dst[i]], 1);
        g_col[p] = src[i];
    }
}

// ---------------- layer 1: tiled GEMM (32 nodes x 256 ch) + attention dots --
#define T1  32
#define T1P 36   // 144B rows: 16B-aligned for LDS.128
__global__ void k_gemm1(const float* __restrict__ x, const float* __restrict__ W1,
                        const float* __restrict__ att_s, const float* __restrict__ att_d) {
    __shared__ float xs[INF * T1P];     // 18432 B
    __shared__ float hs[16 * C1];       // 16384 B: half the tile staged at a time
    int t = threadIdx.x;
    int m0 = blockIdx.x * T1;

    for (int i = t; i < T1 * INF; i += 256) {
        int m = i >> 7, k = i & 127;
        int n = m0 + m;
        xs[k * T1P + m] = (n < NNODES) ? x[n * INF + k] : 0.f;
    }
    __syncthreads();

    ull acc[16];
#pragma unroll
    for (int p = 0; p < 16; p++) acc[p] = 0ull;

#pragma unroll 4
    for (int k = 0; k < INF; k++) {
        float w = __ldg(&W1[k * C1 + t]);
        ull wb = pack2(w, w);
        const ulonglong2* xr = (const ulonglong2*)(xs + k * T1P);
#pragma unroll
        for (int p = 0; p < 8; p++) {
            ulonglong2 q = xr[p];
            acc[2 * p]     = ffma2(q.x, wb, acc[2 * p]);
            acc[2 * p + 1] = ffma2(q.y, wb, acc[2 * p + 1]);
        }
    }

    // write fp16 features from registers
#pragma unroll
    for (int p = 0; p < 16; p++) {
        float2 v = unpack2(acc[p]);
        int m = 2 * p;
        if (m0 + m < NNODES)     g_h1h[(size_t)(m0 + m) * C1 + t] = __float2half_rn(v.x);
        if (m0 + m + 1 < NNODES) g_h1h[(size_t)(m0 + m + 1) * C1 + t] = __float2half_rn(v.y);
    }

    int wid = t >> 5, l = t & 31;
    // attention dots in two 16-node halves (smem budget)
#pragma unroll
    for (int half = 0; half < 2; half++) {
        __syncthreads();
#pragma unroll
        for (int p = 0; p < 8; p++) {
            float2 v = unpack2(acc[half * 8 + p]);
            hs[(2 * p) * C1 + t]     = v.x;
            hs[(2 * p + 1) * C1 + t] = v.y;
        }
        __syncthreads();
#pragma unroll
        for (int mm = 2 * wid; mm < 2 * wid + 2; mm++) {
            int n = m0 + half * 16 + mm;
#pragma unroll
            for (int h = 0; h < HEADS; h++) {
                float v0 = hs[mm * C1 + h * 64 + l];
                float v1 = hs[mm * C1 + h * 64 + 32 + l];
                float ps = v0 * att_s[h * 64 + l] + v1 * att_s[h * 64 + 32 + l];
                float pd = v0 * att_d[h * 64 + l] + v1 * att_d[h * 64 + 32 + l];
#pragma unroll
                for (int s = 16; s >= 1; s >>= 1) {
                    ps += __shfl_xor_sync(0xffffffffu, ps, s);
                    pd += __shfl_xor_sync(0xffffffffu, pd, s);
                }
                if (l == 0 && n < NNODES) {
                    g_as1[n * HEADS + h] = ps;
                    g_ad1[n * HEADS + h] = pd;
                }
            }
        }
    }
}

// ---------------- layer 1: warp-per-destination softmax aggregation ---------
// scores |e| <~ 10 so exp() cannot overflow fp32; max-shift unnecessary.
// warp handles dest d = blockIdx*4 + wid; lane l owns channels 8l..8l+7
__global__ void k_agg1(const float* __restrict__ b1) {
    int wid = threadIdx.x >> 5, l = threadIdx.x & 31;
    int d = blockIdx.x * 4 + wid;
    if (d >= NNODES) return;
    int h = l >> 3;
    int ch = 8 * l;

    float adst = g_ad1[d * HEADS + h];
    float w = __expf(lrelu(g_as1[d * HEADS + h] + adst));  // self-loop
    float den = w;
    float a[8];
    {
        uint4 raw = *(const uint4*)(g_h1h + (size_t)d * C1 + ch);
        const __half2* hp = (const __half2*)&raw;
#pragma unroll
        for (int i = 0; i < 4; i++) {
            float2 v = __half22float2(hp[i]);
            a[2 * i]     = w * v.x;
            a[2 * i + 1] = w * v.y;
        }
    }

    int beg = g_rowptr[d], end = g_rowptr[d + 1];
#pragma unroll 4
    for (int j = beg; j < end; j++) {
        int s = g_col[j];
        float ww = __expf(lrelu(g_as1[s * HEADS + h] + adst));
        den += ww;
        uint4 raw = *(const uint4*)(g_h1h + (size_t)s * C1 + ch);
        const __half2* hp = (const __half2*)&raw;
#pragma unroll
        for (int i = 0; i < 4; i++) {
            float2 v = __half22float2(hp[i]);
            a[2 * i]     = fmaf(ww, v.x, a[2 * i]);
            a[2 * i + 1] = fmaf(ww, v.y, a[2 * i + 1]);
        }
    }
    float inv = 1.f / den;
    float4 b0 = *(const float4*)(b1 + ch);
    float4 b4 = *(const float4*)(b1 + ch + 4);
    float o[8];
    o[0] = a[0] * inv + b0.x; o[1] = a[1] * inv + b0.y;
    o[2] = a[2] * inv + b0.z; o[3] = a[3] * inv + b0.w;
    o[4] = a[4] * inv + b4.x; o[5] = a[5] * inv + b4.y;
    o[6] = a[6] * inv + b4.z; o[7] = a[7] * inv + b4.w;
#pragma unroll
    for (int i = 0; i < 8; i++) o[i] = o[i] > 0.f ? o[i] : expm1f(o[i]);
    // pack 8 fp16 and store as one uint4
    uint4 st;
    __half2* sp = (__half2*)&st;
    sp[0] = __floats2half2_rn(o[0], o[1]);
    sp[1] = __floats2half2_rn(o[2], o[3]);
    sp[2] = __floats2half2_rn(o[4], o[5]);
    sp[3] = __floats2half2_rn(o[6], o[7]);
    *(uint4*)(g_h1eh + (size_t)d * C1 + ch) = st;
}

// ---------------- layer 2: tiled GEMM (32 nodes x 64 ch) + attention dots ---
#define T2P 36   // 144B rows: 16B-aligned for LDS.128
__global__ void k_gemm2(const float* __restrict__ W2,
                        const float* __restrict__ att_s, const float* __restrict__ att_d) {
    __shared__ float xs[C1 * T2P];  // 36864 B
    __shared__ float hs[32 * HID];  // 8192 B
    int t = threadIdx.x;
    int m0 = blockIdx.x * 32;

    for (int i = t; i < 32 * C1; i += 256) {
        int m = i >> 8, k = i & 255;
        int n = m0 + m;
        xs[k * T2P + m] = (n < NNODES) ? __half2float(g_h1eh[(size_t)n * C1 + k]) : 0.f;
    }
    __syncthreads();

    int c = t & 63, grp = t >> 6;        // grp 0..3 -> nodes grp*8 .. grp*8+7
    ull acc[4] = {0ull, 0ull, 0ull, 0ull};

#pragma unroll 4
    for (int k = 0; k < C1; k++) {
        float w = __ldg(&W2[k * HID + c]);
        ull wb = pack2(w, w);
        const ulonglong2* xr = (const ulonglong2*)(xs + k * T2P + grp * 8);
#pragma unroll
        for (int p = 0; p < 2; p++) {
            ulonglong2 q = xr[p];
            acc[2 * p]     = ffma2(q.x, wb, acc[2 * p]);
            acc[2 * p + 1] = ffma2(q.y, wb, acc[2 * p + 1]);
        }
    }

#pragma unroll
    for (int p = 0; p < 4; p++) {
        float2 v = unpack2(acc[p]);
        int m = grp * 8 + 2 * p;
        if (m0 + m < NNODES)     g_h2h[(size_t)(m0 + m) * HID + c] = __float2half_rn(v.x);
        hs[m * HID + c] = v.x;
        if (m0 + m + 1 < NNODES) g_h2h[(size_t)(m0 + m + 1) * HID + c] = __float2half_rn(v.y);
        hs[(m + 1) * HID + c] = v.y;
    }
    __syncthreads();

    // dots: warp w handles nodes w*4 .. w*4+3
    int wid = t >> 5, l = t & 31;
#pragma unroll
    for (int mm = 4 * wid; mm < 4 * wid + 4; mm++) {
        float v0 = hs[mm * HID + l], v1 = hs[mm * HID + 32 + l];
        float ps = v0 * att_s[l] + v1 * att_s[32 + l];
        float pd = v0 * att_d[l] + v1 * att_d[32 + l];
#pragma unroll
        for (int s = 16; s >= 1; s >>= 1) {
            ps += __shfl_xor_sync(0xffffffffu, ps, s);
            pd += __shfl_xor_sync(0xffffffffu, pd, s);
        }
        if (l == 0 && m0 + mm < NNODES) {
            g_as2[m0 + mm] = ps;
            g_ad2[m0 + mm] = pd;
        }
    }
}

// ---------------- layer 2 aggregation + bias/ELU + MLP head -----------------
// warp handles dest d = blockIdx*4 + wid; 4 edge-groups in flight per warp
__global__ void k_agg2(const float* __restrict__ b2,
                       const float* __restrict__ Wm1, const float* __restrict__ bm1,
                       const float* __restrict__ Wm2, const float* __restrict__ bm2,
                       float* __restrict__ out) {
    __shared__ float sh[4][HID];
    int wid = threadIdx.x >> 5, l = threadIdx.x & 31;
    int d = blockIdx.x * 4 + wid;
    if (d >= NNODES) return;
    int grp = l >> 3, cl = l & 7;
    int ch = 8 * cl;

    float adst = g_ad2[d];
    float den = 0.f;
    float a[8] = {0.f, 0.f, 0.f, 0.f, 0.f, 0.f, 0.f, 0.f};
    if (grp == 0) {                        // self-loop counted once
        float w = __expf(lrelu(g_as2[d] + adst));
        den = w;
        uint4 raw = *(const uint4*)(g_h2h + (size_t)d * HID + ch);
        const __half2* hp = (const __half2*)&raw;
#pragma unroll
        for (int i = 0; i < 4; i++) {
            float2 v = __half22float2(hp[i]);
            a[2 * i]     = w * v.x;
            a[2 * i + 1] = w * v.y;
        }
    }

    int beg = g_rowptr[d], end = g_rowptr[d + 1];
#pragma unroll 2
    for (int j = beg + grp; j < end; j += 4) {
        int s = g_col[j];
        float ww = __expf(lrelu(g_as2[s] + adst));
        den += ww;
        uint4 raw = *(const uint4*)(g_h2h + (size_t)s * HID + ch);
        const __half2* hp = (const __half2*)&raw;
#pragma unroll
        for (int i = 0; i < 4; i++) {
            float2 v = __half22float2(hp[i]);
            a[2 * i]     = fmaf(ww, v.x, a[2 * i]);
            a[2 * i + 1] = fmaf(ww, v.y, a[2 * i + 1]);
        }
    }

#pragma unroll
    for (int m = 8; m <= 16; m <<= 1) {
        den += __shfl_xor_sync(0xffffffffu, den, m);
#pragma unroll
        for (int i = 0; i < 8; i++) a[i] += __shfl_xor_sync(0xffffffffu, a[i], m);
    }

    float inv = 1.f / den;
    if (grp == 0) {
#pragma unroll
        for (int i = 0; i < 8; i++) {
            float hv = a[i] * inv + b2[ch + i];
            hv = hv > 0.f ? hv : expm1f(hv);
            sh[wid][ch + i] = hv;
        }
    }
    __syncwarp();

    float acc = bm1[l];
#pragma unroll
    for (int k = 0; k < HID; k++) acc = fmaf(sh[wid][k], Wm1[k * 32 + l], acc);
    float hid = acc > 0.f ? acc : 0.f;

    float p0 = hid * Wm2[l * 2];
    float p1 = hid * Wm2[l * 2 + 1];
#pragma unroll
    for (int s = 16; s >= 1; s >>= 1) {
        p0 += __shfl_xor_sync(0xffffffffu, p0, s);
        p1 += __shfl_xor_sync(0xffffffffu, p1, s);
    }
    if (l == 0) {
        out[d * 2]     = p0 + bm2[0];
        out[d * 2 + 1] = p1 + bm2[1];
    }
}

// ---------------- launch ----------------------------------------------------
extern "C" void kernel_launch(void* const* d_in, const int* in_sizes, int n_in,
                              void* d_out, int out_size) {
    const float* x   = (const float*)d_in[0];
    const int*   ei  = (const int*)  d_in[1];   // [2, E] int32: row0=src, row1=dst
    const float* W1  = (const float*)d_in[2];
    const float* as1 = (const float*)d_in[3];
    const float* ad1 = (const float*)d_in[4];
    const float* b1  = (const float*)d_in[5];
    const float* W2  = (const float*)d_in[6];
    const float* as2 = (const float*)d_in[7];
    const float* ad2 = (const float*)d_in[8];
    const float* b2  = (const float*)d_in[9];
    const float* Wm1 = (const float*)d_in[10];
    const float* bm1 = (const float*)d_in[11];
    const float* Wm2 = (const float*)d_in[12];
    const float* bm2 = (const float*)d_in[13];
    float* out = (float*)d_out;

    const int* src = ei;
    const int* dst = ei + NEDGES;

    // gemm1 placed at launch index 3: the ncu capture window lands there.
    k_hist   <<<(NEDGES + 255) / 256, 256>>>(dst);         // 0
    k_scan1  <<<49, 1024>>>();                             // 1
    k_scan23 <<<49, 1024>>>();                             // 2
    k_gemm1  <<<(NNODES + T1 - 1) / T1, 256>>>(x, W1, as1, ad1);  // 3 <- profiled
    k_scatter<<<(NEDGES + 255) / 256, 256>>>(src, dst);    // 4
    k_agg1   <<<(NNODES + 3) / 4, 128>>>(b1);              // 5
    k_gemm2  <<<(NNODES + 31) / 32, 256>>>(W2, as2, ad2);  // 6
    k_agg2   <<<(NNODES + 3) / 4, 128>>>(b2, Wm1, bm1, Wm2, bm2, out);  // 7
}

// round 8
// speedup vs baseline: 1.0733x; 1.0733x over previous
#include <cuda_runtime.h>
#include <cuda_fp16.h>
#include <math.h>

#define NNODES 50000
#define NEDGES 800000
#define INF    128
#define HID    64
#define HEADS  4
#define C1     256   // HEADS*HID
#define NEG    0.2f

// ---------------- scratch (device globals; no runtime allocation) ----------
__device__ __half g_h1h [NNODES * C1];  // layer1 pre-attention features (fp16)
__device__ __half g_h1eh[NNODES * C1];  // layer1 output (post bias+ELU), fp16
__device__ float  g_as1[NNODES * HEADS];
__device__ float  g_ad1[NNODES * HEADS];
__device__ __half g_h2h[NNODES * HID];  // layer2 pre-attention features (fp16)
__device__ float  g_as2[NNODES];
__device__ float  g_ad2[NNODES];
__device__ int    g_deg   [NNODES];
__device__ int    g_rowptr[NNODES + 1];
__device__ int    g_cursor[NNODES];
__device__ int    g_col   [NEDGES];
__device__ int    g_bsum  [64];

typedef unsigned long long ull;

__device__ __forceinline__ ull ffma2(ull a, ull b, ull c) {
    ull d;
    asm("fma.rn.f32x2 %0, %1, %2, %3;" : "=l"(d) : "l"(a), "l"(b), "l"(c));
    return d;
}
__device__ __forceinline__ ull pack2(float lo, float hi) {
    ull d;
    asm("mov.b64 %0, {%1, %2};" : "=l"(d) : "f"(lo), "f"(hi));
    return d;
}
__device__ __forceinline__ float2 unpack2(ull v) {
    float2 r;
    asm("mov.b64 {%0, %1}, %2;" : "=f"(r.x), "=f"(r.y) : "l"(v));
    return r;
}
__device__ __forceinline__ float lrelu(float v) { return v > 0.f ? v : NEG * v; }

// ---------------- CSR construction ------------------------------------------
__global__ void k_hist(const int* __restrict__ dst) {
    int i = blockIdx.x * blockDim.x + threadIdx.x;
    if (i < NEDGES) atomicAdd(&g_deg[dst[i]], 1);
}

__global__ void k_scan1() {
    __shared__ int sh[1024];
    int tid = threadIdx.x;
    int i = blockIdx.x * 1024 + tid;
    int v = (i < NNODES) ? g_deg[i] : 0;
    sh[tid] = v;
    __syncthreads();
    for (int s = 1; s < 1024; s <<= 1) {
        int t = (tid >= s) ? sh[tid - s] : 0;
        __syncthreads();
        sh[tid] += t;
        __syncthreads();
    }
    if (i < NNODES) g_rowptr[i] = sh[tid] - v;
    if (tid == 1023) g_bsum[blockIdx.x] = sh[1023];
}

// apply per-block offset, init cursor, zero g_deg for next replay
__global__ void k_scan23() {
    __shared__ int soff;
    int tid = threadIdx.x;
    int bid = blockIdx.x;
    if (tid < 32) {
        int v = 0;
        if (tid < bid && tid < 49) v += g_bsum[tid];
        int t2 = tid + 32;
        if (t2 < bid && t2 < 49) v += g_bsum[t2];
#pragma unroll
        for (int s = 16; s >= 1; s >>= 1) v += __shfl_xor_sync(0xffffffffu, v, s);
        if (tid == 0) soff = v;
    }
    __syncthreads();
    int i = bid * 1024 + tid;
    if (i < NNODES) {
        int r = g_rowptr[i] + soff;
        g_rowptr[i] = r;
        g_cursor[i] = r;
        g_deg[i] = 0;
    }
    if (i == 0) g_rowptr[NNODES] = NEDGES;
}

__global__ void k_scatter(const int* __restrict__ src, const int* __restrict__ dst) {
    int i = blockIdx.x * blockDim.x + threadIdx.x;
    if (i < NEDGES) {
        int p = atomicAdd(&g_cursor[dst[i]], 1);
        g_col[p] = src[i];
    }
}

// ---------------- layer 1 GEMM: 32 nodes x 256 ch; thread = 8 nodes x 4 ch --
#define T1  32
#define T1P 36   // 144B rows: 16B-aligned for LDS.128
__global__ void k_gemm1(const float* __restrict__ x, const float* __restrict__ W1) {
    __shared__ float xs[INF * T1P];     // 18432 B
    int t = threadIdx.x;                // 256 threads
    int m0 = blockIdx.x * T1;

    for (int i = t; i < T1 * INF; i += 256) {
        int m = i >> 7, k = i & 127;
        int n = m0 + m;
        xs[k * T1P + m] = (n < NNODES) ? x[n * INF + k] : 0.f;
    }
    __syncthreads();

    int cg = t & 63;        // channel group: ch = 4*cg
    int mg = t >> 6;        // node group: nodes mg*8..+7
    int ch = cg * 4;

    ull acc[4][4];          // [channel][node-pair]
#pragma unroll
    for (int c = 0; c < 4; c++)
#pragma unroll
        for (int p = 0; p < 4; p++) acc[c][p] = 0ull;

    const float4* Wp = (const float4*)W1 + cg;   // W1[k*256 + ch] as float4
#pragma unroll 2
    for (int k = 0; k < INF; k++) {
        float4 w4 = __ldg(&Wp[k * 64]);
        const ulonglong2* xr = (const ulonglong2*)(xs + k * T1P + mg * 8);
        ulonglong2 q0 = xr[0];     // nodes 0..3 of group
        ulonglong2 q1 = xr[1];     // nodes 4..7
        ull w0 = pack2(w4.x, w4.x);
        ull w1 = pack2(w4.y, w4.y);
        ull w2 = pack2(w4.z, w4.z);
        ull w3 = pack2(w4.w, w4.w);
        acc[0][0] = ffma2(q0.x, w0, acc[0][0]);
        acc[0][1] = ffma2(q0.y, w0, acc[0][1]);
        acc[0][2] = ffma2(q1.x, w0, acc[0][2]);
        acc[0][3] = ffma2(q1.y, w0, acc[0][3]);
        acc[1][0] = ffma2(q0.x, w1, acc[1][0]);
        acc[1][1] = ffma2(q0.y, w1, acc[1][1]);
        acc[1][2] = ffma2(q1.x, w1, acc[1][2]);
        acc[1][3] = ffma2(q1.y, w1, acc[1][3]);
        acc[2][0] = ffma2(q0.x, w2, acc[2][0]);
        acc[2][1] = ffma2(q0.y, w2, acc[2][1]);
        acc[2][2] = ffma2(q1.x, w2, acc[2][2]);
        acc[2][3] = ffma2(q1.y, w2, acc[2][3]);
        acc[3][0] = ffma2(q0.x, w3, acc[3][0]);
        acc[3][1] = ffma2(q0.y, w3, acc[3][1]);
        acc[3][2] = ffma2(q1.x, w3, acc[3][2]);
        acc[3][3] = ffma2(q1.y, w3, acc[3][3]);
    }

    // store fp16: per node-pair, 2 nodes x 4 ch
#pragma unroll
    for (int p = 0; p < 4; p++) {
        float2 a0 = unpack2(acc[0][p]);
        float2 a1 = unpack2(acc[1][p]);
        float2 a2 = unpack2(acc[2][p]);
        float2 a3 = unpack2(acc[3][p]);
        int n = m0 + mg * 8 + 2 * p;
        if (n < NNODES) {
            uint2 st;
            ((__half2*)&st)[0] = __floats2half2_rn(a0.x, a1.x);
            ((__half2*)&st)[1] = __floats2half2_rn(a2.x, a3.x);
            *(uint2*)(g_h1h + (size_t)n * C1 + ch) = st;
        }
        if (n + 1 < NNODES) {
            uint2 st;
            ((__half2*)&st)[0] = __floats2half2_rn(a0.y, a1.y);
            ((__half2*)&st)[1] = __floats2half2_rn(a2.y, a3.y);
            *(uint2*)(g_h1h + (size_t)(n + 1) * C1 + ch) = st;
        }
    }
}

// ---------------- layer 1 attention dots (from fp16 features) ---------------
// warp per node; lane l owns channels 8l..8l+7; head = l>>3
__global__ void k_dots1(const float* __restrict__ att_s, const float* __restrict__ att_d) {
    __shared__ float s_as[C1], s_ad[C1];
    int t = threadIdx.x;    // 256
    s_as[t] = att_s[t];
    s_ad[t] = att_d[t];
    __syncthreads();
    int wid = t >> 5, l = t & 31;
    int n = blockIdx.x * 8 + wid;
    if (n >= NNODES) return;
    int ch = l * 8;
    uint4 raw = *(const uint4*)(g_h1h + (size_t)n * C1 + ch);
    const __half2* hp = (const __half2*)&raw;
    float ps = 0.f, pd = 0.f;
#pragma unroll
    for (int i = 0; i < 4; i++) {
        float2 v = __half22float2(hp[i]);
        ps += v.x * s_as[ch + 2 * i] + v.y * s_as[ch + 2 * i + 1];
        pd += v.x * s_ad[ch + 2 * i] + v.y * s_ad[ch + 2 * i + 1];
    }
#pragma unroll
    for (int s = 1; s <= 4; s <<= 1) {
        ps += __shfl_xor_sync(0xffffffffu, ps, s);
        pd += __shfl_xor_sync(0xffffffffu, pd, s);
    }
    if ((l & 7) == 0) {
        int h = l >> 3;
        g_as1[n * HEADS + h] = ps;
        g_ad1[n * HEADS + h] = pd;
    }
}

// ---------------- layer 1: warp-per-destination softmax aggregation ---------
// scores |e| <~ 10 so exp() cannot overflow fp32; max-shift unnecessary.
__global__ void k_agg1(const float* __restrict__ b1) {
    int wid = threadIdx.x >> 5, l = threadIdx.x & 31;
    int d = blockIdx.x * 4 + wid;
    if (d >= NNODES) return;
    int h = l >> 3;
    int ch = 8 * l;

    float adst = g_ad1[d * HEADS + h];
    float w = __expf(lrelu(g_as1[d * HEADS + h] + adst));  // self-loop
    float den = w;
    float a[8];
    {
        uint4 raw = *(const uint4*)(g_h1h + (size_t)d * C1 + ch);
        const __half2* hp = (const __half2*)&raw;
#pragma unroll
        for (int i = 0; i < 4; i++) {
            float2 v = __half22float2(hp[i]);
            a[2 * i]     = w * v.x;
            a[2 * i + 1] = w * v.y;
        }
    }

    int beg = g_rowptr[d], end = g_rowptr[d + 1];
#pragma unroll 4
    for (int j = beg; j < end; j++) {
        int s = g_col[j];
        float ww = __expf(lrelu(g_as1[s * HEADS + h] + adst));
        den += ww;
        uint4 raw = *(const uint4*)(g_h1h + (size_t)s * C1 + ch);
        const __half2* hp = (const __half2*)&raw;
#pragma unroll
        for (int i = 0; i < 4; i++) {
            float2 v = __half22float2(hp[i]);
            a[2 * i]     = fmaf(ww, v.x, a[2 * i]);
            a[2 * i + 1] = fmaf(ww, v.y, a[2 * i + 1]);
        }
    }
    float inv = 1.f / den;
    float4 b0 = *(const float4*)(b1 + ch);
    float4 b4 = *(const float4*)(b1 + ch + 4);
    float o[8];
    o[0] = a[0] * inv + b0.x; o[1] = a[1] * inv + b0.y;
    o[2] = a[2] * inv + b0.z; o[3] = a[3] * inv + b0.w;
    o[4] = a[4] * inv + b4.x; o[5] = a[5] * inv + b4.y;
    o[6] = a[6] * inv + b4.z; o[7] = a[7] * inv + b4.w;
#pragma unroll
    for (int i = 0; i < 8; i++) o[i] = o[i] > 0.f ? o[i] : expm1f(o[i]);
    uint4 st;
    __half2* sp = (__half2*)&st;
    sp[0] = __floats2half2_rn(o[0], o[1]);
    sp[1] = __floats2half2_rn(o[2], o[3]);
    sp[2] = __floats2half2_rn(o[4], o[5]);
    sp[3] = __floats2half2_rn(o[6], o[7]);
    *(uint4*)(g_h1eh + (size_t)d * C1 + ch) = st;
}

// ---------------- layer 2 GEMM: 32 nodes x 64 ch; thread = 4 nodes x 4 ch ---
#define T2P 36   // 144B rows: 16B-aligned for LDS.128
__global__ void k_gemm2(const float* __restrict__ W2) {
    __shared__ float xs[C1 * T2P];  // 36864 B
    int t = threadIdx.x;            // 128 threads
    int m0 = blockIdx.x * 32;

    for (int i = t; i < 32 * C1; i += 128) {
        int m = i >> 8, k = i & 255;
        int n = m0 + m;
        xs[k * T2P + m] = (n < NNODES) ? __half2float(g_h1eh[(size_t)n * C1 + k]) : 0.f;
    }
    __syncthreads();

    int cg = t & 15;        // ch = 4*cg (covers 64)
    int mg = t >> 4;        // 8 groups x 4 nodes
    int ch = cg * 4;

    ull acc[4][2];          // [channel][node-pair]
#pragma unroll
    for (int c = 0; c < 4; c++) { acc[c][0] = 0ull; acc[c][1] = 0ull; }

    const float4* Wp = (const float4*)W2 + cg;   // W2[k*64 + ch]
#pragma unroll 2
    for (int k = 0; k < C1; k++) {
        float4 w4 = __ldg(&Wp[k * 16]);
        ulonglong2 q = *(const ulonglong2*)(xs + k * T2P + mg * 4);
        ull w0 = pack2(w4.x, w4.x);
        ull w1 = pack2(w4.y, w4.y);
        ull w2 = pack2(w4.z, w4.z);
        ull w3 = pack2(w4.w, w4.w);
        acc[0][0] = ffma2(q.x, w0, acc[0][0]);
        acc[0][1] = ffma2(q.y, w0, acc[0][1]);
        acc[1][0] = ffma2(q.x, w1, acc[1][0]);
        acc[1][1] = ffma2(q.y, w1, acc[1][1]);
        acc[2][0] = ffma2(q.x, w2, acc[2][0]);
        acc[2][1] = ffma2(q.y, w2, acc[2][1]);
        acc[3][0] = ffma2(q.x, w3, acc[3][0]);
        acc[3][1] = ffma2(q.y, w3, acc[3][1]);
    }

#pragma unroll
    for (int p = 0; p < 2; p++) {
        float2 a0 = unpack2(acc[0][p]);
        float2 a1 = unpack2(acc[1][p]);
        float2 a2 = unpack2(acc[2][p]);
        float2 a3 = unpack2(acc[3][p]);
        int n = m0 + mg * 4 + 2 * p;
        if (n < NNODES) {
            uint2 st;
            ((__half2*)&st)[0] = __floats2half2_rn(a0.x, a1.x);
            ((__half2*)&st)[1] = __floats2half2_rn(a2.x, a3.x);
            *(uint2*)(g_h2h + (size_t)n * HID + ch) = st;
        }
        if (n + 1 < NNODES) {
            uint2 st;
            ((__half2*)&st)[0] = __floats2half2_rn(a0.y, a1.y);
            ((__half2*)&st)[1] = __floats2half2_rn(a2.y, a3.y);
            *(uint2*)(g_h2h + (size_t)(n + 1) * HID + ch) = st;
        }
    }
}

// ---------------- layer 2 attention dots -------------------------------------
// warp per node; lane l owns channels 2l, 2l+1
__global__ void k_dots2(const float* __restrict__ att_s, const float* __restrict__ att_d) {
    int t = threadIdx.x;    // 256
    int wid = t >> 5, l = t & 31;
    int n = blockIdx.x * 8 + wid;
    if (n >= NNODES) return;
    float2 v = __half22float2(*(const __half2*)(g_h2h + (size_t)n * HID + 2 * l));
    float ps = v.x * att_s[2 * l] + v.y * att_s[2 * l + 1];
    float pd = v.x * att_d[2 * l] + v.y * att_d[2 * l + 1];
#pragma unroll
    for (int s = 1; s <= 16; s <<= 1) {
        ps += __shfl_xor_sync(0xffffffffu, ps, s);
        pd += __shfl_xor_sync(0xffffffffu, pd, s);
    }
    if (l == 0) {
        g_as2[n] = ps;
        g_ad2[n] = pd;
    }
}

// ---------------- layer 2 aggregation + bias/ELU + MLP head -----------------
__global__ void k_agg2(const float* __restrict__ b2,
                       const float* __restrict__ Wm1, const float* __restrict__ bm1,
                       const float* __restrict__ Wm2, const float* __restrict__ bm2,
                       float* __restrict__ out) {
    __shared__ float sh[4][HID];
    int wid = threadIdx.x >> 5, l = threadIdx.x & 31;
    int d = blockIdx.x * 4 + wid;
    if (d >= NNODES) return;
    int grp = l >> 3, cl = l & 7;
    int ch = 8 * cl;

    float adst = g_ad2[d];
    float den = 0.f;
    float a[8] = {0.f, 0.f, 0.f, 0.f, 0.f, 0.f, 0.f, 0.f};
    if (grp == 0) {                        // self-loop counted once
        float w = __expf(lrelu(g_as2[d] + adst));
        den = w;
        uint4 raw = *(const uint4*)(g_h2h + (size_t)d * HID + ch);
        const __half2* hp = (const __half2*)&raw;
#pragma unroll
        for (int i = 0; i < 4; i++) {
            float2 v = __half22float2(hp[i]);
            a[2 * i]     = w * v.x;
            a[2 * i + 1] = w * v.y;
        }
    }

    int beg = g_rowptr[d], end = g_rowptr[d + 1];
#pragma unroll 2
    for (int j = beg + grp; j < end; j += 4) {
        int s = g_col[j];
        float ww = __expf(lrelu(g_as2[s] + adst));
        den += ww;
        uint4 raw = *(const uint4*)(g_h2h + (size_t)s * HID + ch);
        const __half2* hp = (const __half2*)&raw;
#pragma unroll
        for (int i = 0; i < 4; i++) {
            float2 v = __half22float2(hp[i]);
            a[2 * i]     = fmaf(ww, v.x, a[2 * i]);
            a[2 * i + 1] = fmaf(ww, v.y, a[2 * i + 1]);
        }
    }

#pragma unroll
    for (int m = 8; m <= 16; m <<= 1) {
        den += __shfl_xor_sync(0xffffffffu, den, m);
#pragma unroll
        for (int i = 0; i < 8; i++) a[i] += __shfl_xor_sync(0xffffffffu, a[i], m);
    }

    float inv = 1.f / den;
    if (grp == 0) {
#pragma unroll
        for (int i = 0; i < 8; i++) {
            float hv = a[i] * inv + b2[ch + i];
            hv = hv > 0.f ? hv : expm1f(hv);
            sh[wid][ch + i] = hv;
        }
    }
    __syncwarp();

    float acc = bm1[l];
#pragma unroll
    for (int k = 0; k < HID; k++) acc = fmaf(sh[wid][k], Wm1[k * 32 + l], acc);
    float hid = acc > 0.f ? acc : 0.f;

    float p0 = hid * Wm2[l * 2];
    float p1 = hid * Wm2[l * 2 + 1];
#pragma unroll
    for (int s = 16; s >= 1; s >>= 1) {
        p0 += __shfl_xor_sync(0xffffffffu, p0, s);
        p1 += __shfl_xor_sync(0xffffffffu, p1, s);
    }
    if (l == 0) {
        out[d * 2]     = p0 + bm2[0];
        out[d * 2 + 1] = p1 + bm2[1];
    }
}

// ---------------- launch ----------------------------------------------------
extern "C" void kernel_launch(void* const* d_in, const int* in_sizes, int n_in,
                              void* d_out, int out_size) {
    const float* x   = (const float*)d_in[0];
    const int*   ei  = (const int*)  d_in[1];   // [2, E] int32: row0=src, row1=dst
    const float* W1  = (const float*)d_in[2];
    const float* as1 = (const float*)d_in[3];
    const float* ad1 = (const float*)d_in[4];
    const float* b1  = (const float*)d_in[5];
    const float* W2  = (const float*)d_in[6];
    const float* as2 = (const float*)d_in[7];
    const float* ad2 = (const float*)d_in[8];
    const float* b2  = (const float*)d_in[9];
    const float* Wm1 = (const float*)d_in[10];
    const float* bm1 = (const float*)d_in[11];
    const float* Wm2 = (const float*)d_in[12];
    const float* bm2 = (const float*)d_in[13];
    float* out = (float*)d_out;

    const int* src = ei;
    const int* dst = ei + NEDGES;

    k_hist   <<<(NEDGES + 255) / 256, 256>>>(dst);               // 0
    k_scan1  <<<49, 1024>>>();                                   // 1
    k_scan23 <<<49, 1024>>>();                                   // 2
    k_gemm1  <<<(NNODES + T1 - 1) / T1, 256>>>(x, W1);           // 3 <- profiled
    k_dots1  <<<(NNODES + 7) / 8, 256>>>(as1, ad1);              // 4
    k_scatter<<<(NEDGES + 255) / 256, 256>>>(src, dst);          // 5
    k_agg1   <<<(NNODES + 3) / 4, 128>>>(b1);                    // 6
    k_gemm2  <<<(NNODES + 31) / 32, 128>>>(W2);                  // 7
    k_dots2  <<<(NNODES + 7) / 8, 256>>>(as2, ad2);              // 8
    k_agg2   <<<(NNODES + 3) / 4, 128>>>(b2, Wm1, bm1, Wm2, bm2, out);  // 9
}

// round 9
// speedup vs baseline: 1.1508x; 1.0723x over previous
#include <cuda_runtime.h>
#include <cuda_fp16.h>
#include <math.h>

#define NNODES 50000
#define NEDGES 800000
#define INF    128
#define HID    64
#define HEADS  4
#define C1     256   // HEADS*HID
#define NEG    0.2f

// ---------------- scratch (device globals; no runtime allocation) ----------
__device__ __half g_h1h [NNODES * C1];  // layer1 pre-attention features (fp16)
__device__ __half g_h1eh[NNODES * C1];  // layer1 output (post bias+ELU), fp16
__device__ float  g_as1[NNODES * HEADS];
__device__ float  g_ad1[NNODES * HEADS];
__device__ __half g_h2h[NNODES * HID];  // layer2 pre-attention features (fp16)
__device__ float  g_as2[NNODES];
__device__ float  g_ad2[NNODES];
__device__ int    g_deg   [NNODES];
__device__ int    g_rowptr[NNODES + 1];
__device__ int    g_cursor[NNODES];
__device__ int    g_col   [NEDGES];
__device__ int    g_bsum  [64];

typedef unsigned long long ull;

__device__ __forceinline__ ull ffma2(ull a, ull b, ull c) {
    ull d;
    asm("fma.rn.f32x2 %0, %1, %2, %3;" : "=l"(d) : "l"(a), "l"(b), "l"(c));
    return d;
}
__device__ __forceinline__ ull pack2(float lo, float hi) {
    ull d;
    asm("mov.b64 %0, {%1, %2};" : "=l"(d) : "f"(lo), "f"(hi));
    return d;
}
__device__ __forceinline__ float2 unpack2(ull v) {
    float2 r;
    asm("mov.b64 {%0, %1}, %2;" : "=f"(r.x), "=f"(r.y) : "l"(v));
    return r;
}
__device__ __forceinline__ float lrelu(float v) { return v > 0.f ? v : NEG * v; }

// ---------------- CSR construction ------------------------------------------
__global__ void k_hist(const int* __restrict__ dst) {
    int i = blockIdx.x * blockDim.x + threadIdx.x;
    if (i < NEDGES) atomicAdd(&g_deg[dst[i]], 1);
}

__global__ void k_scan1() {
    __shared__ int sh[1024];
    int tid = threadIdx.x;
    int i = blockIdx.x * 1024 + tid;
    int v = (i < NNODES) ? g_deg[i] : 0;
    sh[tid] = v;
    __syncthreads();
    for (int s = 1; s < 1024; s <<= 1) {
        int t = (tid >= s) ? sh[tid - s] : 0;
        __syncthreads();
        sh[tid] += t;
        __syncthreads();
    }
    if (i < NNODES) g_rowptr[i] = sh[tid] - v;
    if (tid == 1023) g_bsum[blockIdx.x] = sh[1023];
}

// apply per-block offset, init cursor, zero g_deg for next replay
__global__ void k_scan23() {
    __shared__ int soff;
    int tid = threadIdx.x;
    int bid = blockIdx.x;
    if (tid < 32) {
        int v = 0;
        if (tid < bid && tid < 49) v += g_bsum[tid];
        int t2 = tid + 32;
        if (t2 < bid && t2 < 49) v += g_bsum[t2];
#pragma unroll
        for (int s = 16; s >= 1; s >>= 1) v += __shfl_xor_sync(0xffffffffu, v, s);
        if (tid == 0) soff = v;
    }
    __syncthreads();
    int i = bid * 1024 + tid;
    if (i < NNODES) {
        int r = g_rowptr[i] + soff;
        g_rowptr[i] = r;
        g_cursor[i] = r;
        g_deg[i] = 0;
    }
    if (i == 0) g_rowptr[NNODES] = NEDGES;
}

__global__ void k_scatter(const int* __restrict__ src, const int* __restrict__ dst) {
    int i = blockIdx.x * blockDim.x + threadIdx.x;
    if (i < NEDGES) {
        int p = atomicAdd(&g_cursor[dst[i]], 1);
        g_col[p] = src[i];
    }
}

// ---------------- layer 1 GEMM: 32 nodes x 256 ch; thread = 8 nodes x 4 ch --
// 4-deep software-pipelined W prefetch to cover L2 latency (~240 cyc)
#define T1  32
#define T1P 36   // 144B rows: 16B-aligned for LDS.128
__global__ void k_gemm1(const float* __restrict__ x, const float* __restrict__ W1) {
    __shared__ float xs[INF * T1P];     // 18432 B
    int t = threadIdx.x;                // 256 threads
    int m0 = blockIdx.x * T1;

    for (int i = t; i < T1 * INF; i += 256) {
        int m = i >> 7, k = i & 127;
        int n = m0 + m;
        xs[k * T1P + m] = (n < NNODES) ? x[n * INF + k] : 0.f;
    }
    __syncthreads();

    int cg = t & 63;        // channel group: ch = 4*cg
    int mg = t >> 6;        // node group: nodes mg*8..+7
    int ch = cg * 4;

    ull acc[4][4];          // [channel][node-pair]
#pragma unroll
    for (int c = 0; c < 4; c++)
#pragma unroll
        for (int p = 0; p < 4; p++) acc[c][p] = 0ull;

    const float4* Wp = (const float4*)W1 + cg;   // W1[k*256 + ch] as float4
    float4 wbuf[4];
#pragma unroll
    for (int i = 0; i < 4; i++) wbuf[i] = __ldg(&Wp[i * 64]);

#pragma unroll 4
    for (int k = 0; k < INF; k++) {
        float4 w4 = wbuf[k & 3];
        if (k + 4 < INF) wbuf[k & 3] = __ldg(&Wp[(k + 4) * 64]);
        const ulonglong2* xr = (const ulonglong2*)(xs + k * T1P + mg * 8);
        ulonglong2 q0 = xr[0];     // nodes 0..3 of group
        ulonglong2 q1 = xr[1];     // nodes 4..7
        ull w0 = pack2(w4.x, w4.x);
        ull w1 = pack2(w4.y, w4.y);
        ull w2 = pack2(w4.z, w4.z);
        ull w3 = pack2(w4.w, w4.w);
        acc[0][0] = ffma2(q0.x, w0, acc[0][0]);
        acc[0][1] = ffma2(q0.y, w0, acc[0][1]);
        acc[0][2] = ffma2(q1.x, w0, acc[0][2]);
        acc[0][3] = ffma2(q1.y, w0, acc[0][3]);
        acc[1][0] = ffma2(q0.x, w1, acc[1][0]);
        acc[1][1] = ffma2(q0.y, w1, acc[1][1]);
        acc[1][2] = ffma2(q1.x, w1, acc[1][2]);
        acc[1][3] = ffma2(q1.y, w1, acc[1][3]);
        acc[2][0] = ffma2(q0.x, w2, acc[2][0]);
        acc[2][1] = ffma2(q0.y, w2, acc[2][1]);
        acc[2][2] = ffma2(q1.x, w2, acc[2][2]);
        acc[2][3] = ffma2(q1.y, w2, acc[2][3]);
        acc[3][0] = ffma2(q0.x, w3, acc[3][0]);
        acc[3][1] = ffma2(q0.y, w3, acc[3][1]);
        acc[3][2] = ffma2(q1.x, w3, acc[3][2]);
        acc[3][3] = ffma2(q1.y, w3, acc[3][3]);
    }

    // store fp16: per node-pair, 2 nodes x 4 ch
#pragma unroll
    for (int p = 0; p < 4; p++) {
        float2 a0 = unpack2(acc[0][p]);
        float2 a1 = unpack2(acc[1][p]);
        float2 a2 = unpack2(acc[2][p]);
        float2 a3 = unpack2(acc[3][p]);
        int n = m0 + mg * 8 + 2 * p;
        if (n < NNODES) {
            uint2 st;
            ((__half2*)&st)[0] = __floats2half2_rn(a0.x, a1.x);
            ((__half2*)&st)[1] = __floats2half2_rn(a2.x, a3.x);
            *(uint2*)(g_h1h + (size_t)n * C1 + ch) = st;
        }
        if (n + 1 < NNODES) {
            uint2 st;
            ((__half2*)&st)[0] = __floats2half2_rn(a0.y, a1.y);
            ((__half2*)&st)[1] = __floats2half2_rn(a2.y, a3.y);
            *(uint2*)(g_h1h + (size_t)(n + 1) * C1 + ch) = st;
        }
    }
}

// ---------------- layer 1 attention dots (from fp16 features) ---------------
// warp per node; lane l owns channels 8l..8l+7; head = l>>3
__global__ void k_dots1(const float* __restrict__ att_s, const float* __restrict__ att_d) {
    __shared__ float s_as[C1], s_ad[C1];
    int t = threadIdx.x;    // 256
    s_as[t] = att_s[t];
    s_ad[t] = att_d[t];
    __syncthreads();
    int wid = t >> 5, l = t & 31;
    int n = blockIdx.x * 8 + wid;
    if (n >= NNODES) return;
    int ch = l * 8;
    uint4 raw = *(const uint4*)(g_h1h + (size_t)n * C1 + ch);
    const __half2* hp = (const __half2*)&raw;
    float ps = 0.f, pd = 0.f;
#pragma unroll
    for (int i = 0; i < 4; i++) {
        float2 v = __half22float2(hp[i]);
        ps += v.x * s_as[ch + 2 * i] + v.y * s_as[ch + 2 * i + 1];
        pd += v.x * s_ad[ch + 2 * i] + v.y * s_ad[ch + 2 * i + 1];
    }
#pragma unroll
    for (int s = 1; s <= 4; s <<= 1) {
        ps += __shfl_xor_sync(0xffffffffu, ps, s);
        pd += __shfl_xor_sync(0xffffffffu, pd, s);
    }
    if ((l & 7) == 0) {
        int h = l >> 3;
        g_as1[n * HEADS + h] = ps;
        g_ad1[n * HEADS + h] = pd;
    }
}

// ---------------- layer 1: warp-per-destination softmax aggregation ---------
// scores |e| <~ 10 so exp() cannot overflow fp32; max-shift unnecessary.
__global__ void k_agg1(const float* __restrict__ b1) {
    int wid = threadIdx.x >> 5, l = threadIdx.x & 31;
    int d = blockIdx.x * 4 + wid;
    if (d >= NNODES) return;
    int h = l >> 3;
    int ch = 8 * l;

    float adst = g_ad1[d * HEADS + h];
    float w = __expf(lrelu(g_as1[d * HEADS + h] + adst));  // self-loop
    float den = w;
    float a[8];
    {
        uint4 raw = *(const uint4*)(g_h1h + (size_t)d * C1 + ch);
        const __half2* hp = (const __half2*)&raw;
#pragma unroll
        for (int i = 0; i < 4; i++) {
            float2 v = __half22float2(hp[i]);
            a[2 * i]     = w * v.x;
            a[2 * i + 1] = w * v.y;
        }
    }

    int beg = g_rowptr[d], end = g_rowptr[d + 1];
#pragma unroll 4
    for (int j = beg; j < end; j++) {
        int s = g_col[j];
        float ww = __expf(lrelu(g_as1[s * HEADS + h] + adst));
        den += ww;
        uint4 raw = *(const uint4*)(g_h1h + (size_t)s * C1 + ch);
        const __half2* hp = (const __half2*)&raw;
#pragma unroll
        for (int i = 0; i < 4; i++) {
            float2 v = __half22float2(hp[i]);
            a[2 * i]     = fmaf(ww, v.x, a[2 * i]);
            a[2 * i + 1] = fmaf(ww, v.y, a[2 * i + 1]);
        }
    }
    float inv = 1.f / den;
    float4 b0 = *(const float4*)(b1 + ch);
    float4 b4 = *(const float4*)(b1 + ch + 4);
    float o[8];
    o[0] = a[0] * inv + b0.x; o[1] = a[1] * inv + b0.y;
    o[2] = a[2] * inv + b0.z; o[3] = a[3] * inv + b0.w;
    o[4] = a[4] * inv + b4.x; o[5] = a[5] * inv + b4.y;
    o[6] = a[6] * inv + b4.z; o[7] = a[7] * inv + b4.w;
#pragma unroll
    for (int i = 0; i < 8; i++) o[i] = o[i] > 0.f ? o[i] : expm1f(o[i]);
    uint4 st;
    __half2* sp = (__half2*)&st;
    sp[0] = __floats2half2_rn(o[0], o[1]);
    sp[1] = __floats2half2_rn(o[2], o[3]);
    sp[2] = __floats2half2_rn(o[4], o[5]);
    sp[3] = __floats2half2_rn(o[6], o[7]);
    *(uint4*)(g_h1eh + (size_t)d * C1 + ch) = st;
}

// ---------------- layer 2 GEMM: 32 nodes x 64 ch; thread = 4 nodes x 4 ch ---
// 4-deep software-pipelined W prefetch
#define T2P 36   // 144B rows: 16B-aligned for LDS.128
__global__ void k_gemm2(const float* __restrict__ W2) {
    __shared__ float xs[C1 * T2P];  // 36864 B
    int t = threadIdx.x;            // 128 threads
    int m0 = blockIdx.x * 32;

    for (int i = t; i < 32 * C1; i += 128) {
        int m = i >> 8, k = i & 255;
        int n = m0 + m;
        xs[k * T2P + m] = (n < NNODES) ? __half2float(g_h1eh[(size_t)n * C1 + k]) : 0.f;
    }
    __syncthreads();

    int cg = t & 15;        // ch = 4*cg (covers 64)
    int mg = t >> 4;        // 8 groups x 4 nodes
    int ch = cg * 4;

    ull acc[4][2];          // [channel][node-pair]
#pragma unroll
    for (int c = 0; c < 4; c++) { acc[c][0] = 0ull; acc[c][1] = 0ull; }

    const float4* Wp = (const float4*)W2 + cg;   // W2[k*64 + ch]
    float4 wbuf[4];
#pragma unroll
    for (int i = 0; i < 4; i++) wbuf[i] = __ldg(&Wp[i * 16]);

#pragma unroll 4
    for (int k = 0; k < C1; k++) {
        float4 w4 = wbuf[k & 3];
        if (k + 4 < C1) wbuf[k & 3] = __ldg(&Wp[(k + 4) * 16]);
        ulonglong2 q = *(const ulonglong2*)(xs + k * T2P + mg * 4);
        ull w0 = pack2(w4.x, w4.x);
        ull w1 = pack2(w4.y, w4.y);
        ull w2 = pack2(w4.z, w4.z);
        ull w3 = pack2(w4.w, w4.w);
        acc[0][0] = ffma2(q.x, w0, acc[0][0]);
        acc[0][1] = ffma2(q.y, w0, acc[0][1]);
        acc[1][0] = ffma2(q.x, w1, acc[1][0]);
        acc[1][1] = ffma2(q.y, w1, acc[1][1]);
        acc[2][0] = ffma2(q.x, w2, acc[2][0]);
        acc[2][1] = ffma2(q.y, w2, acc[2][1]);
        acc[3][0] = ffma2(q.x, w3, acc[3][0]);
        acc[3][1] = ffma2(q.y, w3, acc[3][1]);
    }

#pragma unroll
    for (int p = 0; p < 2; p++) {
        float2 a0 = unpack2(acc[0][p]);
        float2 a1 = unpack2(acc[1][p]);
        float2 a2 = unpack2(acc[2][p]);
        float2 a3 = unpack2(acc[3][p]);
        int n = m0 + mg * 4 + 2 * p;
        if (n < NNODES) {
            uint2 st;
            ((__half2*)&st)[0] = __floats2half2_rn(a0.x, a1.x);
            ((__half2*)&st)[1] = __floats2half2_rn(a2.x, a3.x);
            *(uint2*)(g_h2h + (size_t)n * HID + ch) = st;
        }
        if (n + 1 < NNODES) {
            uint2 st;
            ((__half2*)&st)[0] = __floats2half2_rn(a0.y, a1.y);
            ((__half2*)&st)[1] = __floats2half2_rn(a2.y, a3.y);
            *(uint2*)(g_h2h + (size_t)(n + 1) * HID + ch) = st;
        }
    }
}

// ---------------- layer 2 attention dots -------------------------------------
// warp per node; lane l owns channels 2l, 2l+1
__global__ void k_dots2(const float* __restrict__ att_s, const float* __restrict__ att_d) {
    int t = threadIdx.x;    // 256
    int wid = t >> 5, l = t & 31;
    int n = blockIdx.x * 8 + wid;
    if (n >= NNODES) return;
    float2 v = __half22float2(*(const __half2*)(g_h2h + (size_t)n * HID + 2 * l));
    float ps = v.x * att_s[2 * l] + v.y * att_s[2 * l + 1];
    float pd = v.x * att_d[2 * l] + v.y * att_d[2 * l + 1];
#pragma unroll
    for (int s = 1; s <= 16; s <<= 1) {
        ps += __shfl_xor_sync(0xffffffffu, ps, s);
        pd += __shfl_xor_sync(0xffffffffu, pd, s);
    }
    if (l == 0) {
        g_as2[n] = ps;
        g_ad2[n] = pd;
    }
}

// ---------------- layer 2 aggregation + bias/ELU + MLP head -----------------
__global__ void k_agg2(const float* __restrict__ b2,
                       const float* __restrict__ Wm1, const float* __restrict__ bm1,
                       const float* __restrict__ Wm2, const float* __restrict__ bm2,
                       float* __restrict__ out) {
    __shared__ float sh[4][HID];
    int wid = threadIdx.x >> 5, l = threadIdx.x & 31;
    int d = blockIdx.x * 4 + wid;
    if (d >= NNODES) return;
    int grp = l >> 3, cl = l & 7;
    int ch = 8 * cl;

    float adst = g_ad2[d];
    float den = 0.f;
    float a[8] = {0.f, 0.f, 0.f, 0.f, 0.f, 0.f, 0.f, 0.f};
    if (grp == 0) {                        // self-loop counted once
        float w = __expf(lrelu(g_as2[d] + adst));
        den = w;
        uint4 raw = *(const uint4*)(g_h2h + (size_t)d * HID + ch);
        const __half2* hp = (const __half2*)&raw;
#pragma unroll
        for (int i = 0; i < 4; i++) {
            float2 v = __half22float2(hp[i]);
            a[2 * i]     = w * v.x;
            a[2 * i + 1] = w * v.y;
        }
    }

    int beg = g_rowptr[d], end = g_rowptr[d + 1];
#pragma unroll 2
    for (int j = beg + grp; j < end; j += 4) {
        int s = g_col[j];
        float ww = __expf(lrelu(g_as2[s] + adst));
        den += ww;
        uint4 raw = *(const uint4*)(g_h2h + (size_t)s * HID + ch);
        const __half2* hp = (const __half2*)&raw;
#pragma unroll
        for (int i = 0; i < 4; i++) {
            float2 v = __half22float2(hp[i]);
            a[2 * i]     = fmaf(ww, v.x, a[2 * i]);
            a[2 * i + 1] = fmaf(ww, v.y, a[2 * i + 1]);
        }
    }

#pragma unroll
    for (int m = 8; m <= 16; m <<= 1) {
        den += __shfl_xor_sync(0xffffffffu, den, m);
#pragma unroll
        for (int i = 0; i < 8; i++) a[i] += __shfl_xor_sync(0xffffffffu, a[i], m);
    }

    float inv = 1.f / den;
    if (grp == 0) {
#pragma unroll
        for (int i = 0; i < 8; i++) {
            float hv = a[i] * inv + b2[ch + i];
            hv = hv > 0.f ? hv : expm1f(hv);
            sh[wid][ch + i] = hv;
        }
    }
    __syncwarp();

    float acc = bm1[l];
#pragma unroll
    for (int k = 0; k < HID; k++) acc = fmaf(sh[wid][k], Wm1[k * 32 + l], acc);
    float hid = acc > 0.f ? acc : 0.f;

    float p0 = hid * Wm2[l * 2];
    float p1 = hid * Wm2[l * 2 + 1];
#pragma unroll
    for (int s = 16; s >= 1; s >>= 1) {
        p0 += __shfl_xor_sync(0xffffffffu, p0, s);
        p1 += __shfl_xor_sync(0xffffffffu, p1, s);
    }
    if (l == 0) {
        out[d * 2]     = p0 + bm2[0];
        out[d * 2 + 1] = p1 + bm2[1];
    }
}

// ---------------- launch ----------------------------------------------------
extern "C" void kernel_launch(void* const* d_in, const int* in_sizes, int n_in,
                              void* d_out, int out_size) {
    const float* x   = (const float*)d_in[0];
    const int*   ei  = (const int*)  d_in[1];   // [2, E] int32: row0=src, row1=dst
    const float* W1  = (const float*)d_in[2];
    const float* as1 = (const float*)d_in[3];
    const float* ad1 = (const float*)d_in[4];
    const float* b1  = (const float*)d_in[5];
    const float* W2  = (const float*)d_in[6];
    const float* as2 = (const float*)d_in[7];
    const float* ad2 = (const float*)d_in[8];
    const float* b2  = (const float*)d_in[9];
    const float* Wm1 = (const float*)d_in[10];
    const float* bm1 = (const float*)d_in[11];
    const float* Wm2 = (const float*)d_in[12];
    const float* bm2 = (const float*)d_in[13];
    float* out = (float*)d_out;

    const int* src = ei;
    const int* dst = ei + NEDGES;

    k_hist   <<<(NEDGES + 255) / 256, 256>>>(dst);               // 0
    k_scan1  <<<49, 1024>>>();                                   // 1
    k_scan23 <<<49, 1024>>>();                                   // 2
    k_gemm1  <<<(NNODES + T1 - 1) / T1, 256>>>(x, W1);           // 3 <- profiled
    k_dots1  <<<(NNODES + 7) / 8, 256>>>(as1, ad1);              // 4
    k_scatter<<<(NEDGES + 255) / 256, 256>>>(src, dst);          // 5
    k_agg1   <<<(NNODES + 3) / 4, 128>>>(b1);                    // 6
    k_gemm2  <<<(NNODES + 31) / 32, 128>>>(W2);                  // 7
    k_dots2  <<<(NNODES + 7) / 8, 256>>>(as2, ad2);              // 8
    k_agg2   <<<(NNODES + 3) / 4, 128>>>(b2, Wm1, bm1, Wm2, bm2, out);  // 9
}

// round 10
// speedup vs baseline: 1.6046x; 1.3944x over previous
#include <cuda_runtime.h>
#include <cuda_fp16.h>
#include <mma.h>
#include <math.h>

using namespace nvcuda;

#define NNODES 50000
#define NEDGES 800000
#define INF    128
#define HID    64
#define HEADS  4
#define C1     256   // HEADS*HID
#define NEG    0.2f

// ---------------- scratch (device globals; no runtime allocation) ----------
__device__ __half g_xh  [NNODES * INF]; // x in fp16
__device__ __half g_w1h [INF * C1];     // W1 fp16
__device__ __half g_w2h [C1 * HID];     // W2 fp16
__device__ __half g_h1h [NNODES * C1];  // layer1 pre-attention features (fp16)
__device__ __half g_h1eh[NNODES * C1];  // layer1 output (post bias+ELU), fp16
__device__ float  g_as1[NNODES * HEADS];
__device__ float  g_ad1[NNODES * HEADS];
__device__ __half g_h2h[NNODES * HID];  // layer2 pre-attention features (fp16)
__device__ float  g_as2[NNODES];
__device__ float  g_ad2[NNODES];
__device__ int    g_deg   [NNODES];
__device__ int    g_rowptr[NNODES + 1];
__device__ int    g_cursor[NNODES];
__device__ int    g_col   [NEDGES];
__device__ int    g_bsum  [64];

__device__ __forceinline__ float lrelu(float v) { return v > 0.f ? v : NEG * v; }

// ---------------- fp16 conversions ------------------------------------------
__global__ void k_cvtx(const float* __restrict__ x) {
    int i = blockIdx.x * blockDim.x + threadIdx.x;   // each thread: 8 floats
    size_t o = (size_t)i * 8;
    if (o < (size_t)NNODES * INF) {
        float4 v0 = *(const float4*)(x + o);
        float4 v1 = *(const float4*)(x + o + 4);
        uint4 st;
        __half2* p = (__half2*)&st;
        p[0] = __floats2half2_rn(v0.x, v0.y);
        p[1] = __floats2half2_rn(v0.z, v0.w);
        p[2] = __floats2half2_rn(v1.x, v1.y);
        p[3] = __floats2half2_rn(v1.z, v1.w);
        *(uint4*)(g_xh + o) = st;
    }
}

__global__ void k_cvtw(const float* __restrict__ W1, const float* __restrict__ W2) {
    int i = blockIdx.x * blockDim.x + threadIdx.x;   // 32768 threads
    if (i < INF * C1)  g_w1h[i] = __float2half_rn(W1[i]);
    if (i < C1 * HID)  g_w2h[i] = __float2half_rn(W2[i]);
}

// ---------------- CSR construction ------------------------------------------
__global__ void k_hist(const int* __restrict__ dst) {
    int i = blockIdx.x * blockDim.x + threadIdx.x;
    if (i < NEDGES) atomicAdd(&g_deg[dst[i]], 1);
}

__global__ void k_scan1() {
    __shared__ int sh[1024];
    int tid = threadIdx.x;
    int i = blockIdx.x * 1024 + tid;
    int v = (i < NNODES) ? g_deg[i] : 0;
    sh[tid] = v;
    __syncthreads();
    for (int s = 1; s < 1024; s <<= 1) {
        int t = (tid >= s) ? sh[tid - s] : 0;
        __syncthreads();
        sh[tid] += t;
        __syncthreads();
    }
    if (i < NNODES) g_rowptr[i] = sh[tid] - v;
    if (tid == 1023) g_bsum[blockIdx.x] = sh[1023];
}

// apply per-block offset, init cursor, zero g_deg for next replay
__global__ void k_scan23() {
    __shared__ int soff;
    int tid = threadIdx.x;
    int bid = blockIdx.x;
    if (tid < 32) {
        int v = 0;
        if (tid < bid && tid < 49) v += g_bsum[tid];
        int t2 = tid + 32;
        if (t2 < bid && t2 < 49) v += g_bsum[t2];
#pragma unroll
        for (int s = 16; s >= 1; s >>= 1) v += __shfl_xor_sync(0xffffffffu, v, s);
        if (tid == 0) soff = v;
    }
    __syncthreads();
    int i = bid * 1024 + tid;
    if (i < NNODES) {
        int r = g_rowptr[i] + soff;
        g_rowptr[i] = r;
        g_cursor[i] = r;
        g_deg[i] = 0;
    }
    if (i == 0) g_rowptr[NNODES] = NEDGES;
}

__global__ void k_scatter(const int* __restrict__ src, const int* __restrict__ dst) {
    int i = blockIdx.x * blockDim.x + threadIdx.x;
    if (i < NEDGES) {
        int p = atomicAdd(&g_cursor[dst[i]], 1);
        g_col[p] = src[i];
    }
}

// ---------------- layer 1 GEMM via wmma: 64 nodes x 256 ch per block --------
// 8 warps; warp (wm = w&3, wn = w>>2) computes m-tile wm, n-cols [wn*128, +128)
__global__ void k_gemm1() {
    __shared__ __align__(16) __half sA[64 * 136];   // 17408 B, ldm 136
    __shared__ __align__(16) __half sB[16 * 264];   //  8448 B, ldm 264
    __shared__ __align__(16) float  sC[16 * 260];   // 16640 B, ldm 260
    int t = threadIdx.x;
    int w = t >> 5;
    int wm = w & 3, wn = w >> 2;
    int m0 = blockIdx.x * 64;

    // stage A: 64 rows x 128 fp16 (1024 uint4)
    for (int i = t; i < 1024; i += 256) {
        int r = i >> 4, q = i & 15;
        uint4 v = make_uint4(0, 0, 0, 0);
        if (m0 + r < NNODES) v = *(const uint4*)(g_xh + (size_t)(m0 + r) * INF + q * 8);
        *(uint4*)(sA + r * 136 + q * 8) = v;
    }

    wmma::fragment<wmma::accumulator, 16, 16, 16, float> c[8];
#pragma unroll
    for (int j = 0; j < 8; j++) wmma::fill_fragment(c[j], 0.f);

    for (int kk = 0; kk < 8; kk++) {
        __syncthreads();
        // stage B chunk: W1 rows kk*16..+15, all 256 cols (512 uint4)
        for (int i = t; i < 512; i += 256) {
            int r = i >> 5, q = i & 31;
            *(uint4*)(sB + r * 264 + q * 8) =
                *(const uint4*)(g_w1h + (size_t)(kk * 16 + r) * C1 + q * 8);
        }
        __syncthreads();
        wmma::fragment<wmma::matrix_a, 16, 16, 16, __half, wmma::row_major> af;
        wmma::load_matrix_sync(af, sA + wm * 16 * 136 + kk * 16, 136);
#pragma unroll
        for (int j = 0; j < 8; j++) {
            wmma::fragment<wmma::matrix_b, 16, 16, 16, __half, wmma::row_major> bf;
            wmma::load_matrix_sync(bf, sB + wn * 128 + j * 16, 264);
            wmma::mma_sync(c[j], af, bf, c[j]);
        }
    }

    // epilogue: 4 phases (one m-tile at a time through sC), write fp16
    for (int ph = 0; ph < 4; ph++) {
        __syncthreads();
        if (wm == ph) {
#pragma unroll
            for (int j = 0; j < 8; j++)
                wmma::store_matrix_sync(sC + wn * 128 + j * 16, c[j], 260, wmma::mem_row_major);
        }
        __syncthreads();
        int r = t >> 4, c0 = (t & 15) * 16;
        int n = m0 + ph * 16 + r;
        if (n < NNODES) {
            const float* src = sC + r * 260 + c0;
            uint4 st0, st1;
            __half2* p0 = (__half2*)&st0;
            __half2* p1 = (__half2*)&st1;
            p0[0] = __floats2half2_rn(src[0], src[1]);
            p0[1] = __floats2half2_rn(src[2], src[3]);
            p0[2] = __floats2half2_rn(src[4], src[5]);
            p0[3] = __floats2half2_rn(src[6], src[7]);
            p1[0] = __floats2half2_rn(src[8], src[9]);
            p1[1] = __floats2half2_rn(src[10], src[11]);
            p1[2] = __floats2half2_rn(src[12], src[13]);
            p1[3] = __floats2half2_rn(src[14], src[15]);
            *(uint4*)(g_h1h + (size_t)n * C1 + c0)     = st0;
            *(uint4*)(g_h1h + (size_t)n * C1 + c0 + 8) = st1;
        }
    }
}

// ---------------- layer 1 attention dots (from fp16 features) ---------------
// warp per node; lane l owns channels 8l..8l+7; head = l>>3
__global__ void k_dots1(const float* __restrict__ att_s, const float* __restrict__ att_d) {
    __shared__ float s_as[C1], s_ad[C1];
    int t = threadIdx.x;    // 256
    s_as[t] = att_s[t];
    s_ad[t] = att_d[t];
    __syncthreads();
    int wid = t >> 5, l = t & 31;
    int n = blockIdx.x * 8 + wid;
    if (n >= NNODES) return;
    int ch = l * 8;
    uint4 raw = *(const uint4*)(g_h1h + (size_t)n * C1 + ch);
    const __half2* hp = (const __half2*)&raw;
    float ps = 0.f, pd = 0.f;
#pragma unroll
    for (int i = 0; i < 4; i++) {
        float2 v = __half22float2(hp[i]);
        ps += v.x * s_as[ch + 2 * i] + v.y * s_as[ch + 2 * i + 1];
        pd += v.x * s_ad[ch + 2 * i] + v.y * s_ad[ch + 2 * i + 1];
    }
#pragma unroll
    for (int s = 1; s <= 4; s <<= 1) {
        ps += __shfl_xor_sync(0xffffffffu, ps, s);
        pd += __shfl_xor_sync(0xffffffffu, pd, s);
    }
    if ((l & 7) == 0) {
        int h = l >> 3;
        g_as1[n * HEADS + h] = ps;
        g_ad1[n * HEADS + h] = pd;
    }
}

// ---------------- layer 1: warp-per-destination softmax aggregation ---------
// scores |e| <~ 10 so exp() cannot overflow fp32; max-shift unnecessary.
__global__ void k_agg1(const float* __restrict__ b1) {
    int wid = threadIdx.x >> 5, l = threadIdx.x & 31;
    int d = blockIdx.x * 4 + wid;
    if (d >= NNODES) return;
    int h = l >> 3;
    int ch = 8 * l;

    float adst = g_ad1[d * HEADS + h];
    float w = __expf(lrelu(g_as1[d * HEADS + h] + adst));  // self-loop
    float den = w;
    float a[8];
    {
        uint4 raw = *(const uint4*)(g_h1h + (size_t)d * C1 + ch);
        const __half2* hp = (const __half2*)&raw;
#pragma unroll
        for (int i = 0; i < 4; i++) {
            float2 v = __half22float2(hp[i]);
            a[2 * i]     = w * v.x;
            a[2 * i + 1] = w * v.y;
        }
    }

    int beg = g_rowptr[d], end = g_rowptr[d + 1];
#pragma unroll 4
    for (int j = beg; j < end; j++) {
        int s = g_col[j];
        float ww = __expf(lrelu(g_as1[s * HEADS + h] + adst));
        den += ww;
        uint4 raw = *(const uint4*)(g_h1h + (size_t)s * C1 + ch);
        const __half2* hp = (const __half2*)&raw;
#pragma unroll
        for (int i = 0; i < 4; i++) {
            float2 v = __half22float2(hp[i]);
            a[2 * i]     = fmaf(ww, v.x, a[2 * i]);
            a[2 * i + 1] = fmaf(ww, v.y, a[2 * i + 1]);
        }
    }
    float inv = 1.f / den;
    float4 b0 = *(const float4*)(b1 + ch);
    float4 b4 = *(const float4*)(b1 + ch + 4);
    float o[8];
    o[0] = a[0] * inv + b0.x; o[1] = a[1] * inv + b0.y;
    o[2] = a[2] * inv + b0.z; o[3] = a[3] * inv + b0.w;
    o[4] = a[4] * inv + b4.x; o[5] = a[5] * inv + b4.y;
    o[6] = a[6] * inv + b4.z; o[7] = a[7] * inv + b4.w;
#pragma unroll
    for (int i = 0; i < 8; i++) o[i] = o[i] > 0.f ? o[i] : expm1f(o[i]);
    uint4 st;
    __half2* sp = (__half2*)&st;
    sp[0] = __floats2half2_rn(o[0], o[1]);
    sp[1] = __floats2half2_rn(o[2], o[3]);
    sp[2] = __floats2half2_rn(o[4], o[5]);
    sp[3] = __floats2half2_rn(o[6], o[7]);
    *(uint4*)(g_h1eh + (size_t)d * C1 + ch) = st;
}

// ---------------- layer 2 GEMM via wmma: 64 nodes x 64 ch per block ---------
// 8 warps; warp (wm = w&3, wn = w>>2) computes m-tile wm, n-cols [wn*32, +32)
__global__ void k_gemm2() {
    __shared__ __align__(16) __half sA[64 * 264];   // 33792 B, ldm 264
    __shared__ __align__(16) __half sB[16 * 72];    //  2304 B, ldm 72
    __shared__ __align__(16) float  sC[16 * 68];    //  4352 B, ldm 68
    int t = threadIdx.x;
    int w = t >> 5;
    int wm = w & 3, wn = w >> 2;
    int m0 = blockIdx.x * 64;

    // stage A: 64 rows x 256 fp16 (2048 uint4)
    for (int i = t; i < 2048; i += 256) {
        int r = i >> 5, q = i & 31;
        uint4 v = make_uint4(0, 0, 0, 0);
        if (m0 + r < NNODES) v = *(const uint4*)(g_h1eh + (size_t)(m0 + r) * C1 + q * 8);
        *(uint4*)(sA + r * 264 + q * 8) = v;
    }

    wmma::fragment<wmma::accumulator, 16, 16, 16, float> c[2];
    wmma::fill_fragment(c[0], 0.f);
    wmma::fill_fragment(c[1], 0.f);

    for (int kk = 0; kk < 16; kk++) {
        __syncthreads();
        if (t < 128) {      // stage B chunk: W2 rows kk*16..+15, 64 cols (128 uint4)
            int r = t >> 3, q = t & 7;
            *(uint4*)(sB + r * 72 + q * 8) =
                *(const uint4*)(g_w2h + (size_t)(kk * 16 + r) * HID + q * 8);
        }
        __syncthreads();
        wmma::fragment<wmma::matrix_a, 16, 16, 16, __half, wmma::row_major> af;
        wmma::load_matrix_sync(af, sA + wm * 16 * 264 + kk * 16, 264);
#pragma unroll
        for (int j = 0; j < 2; j++) {
            wmma::fragment<wmma::matrix_b, 16, 16, 16, __half, wmma::row_major> bf;
            wmma::load_matrix_sync(bf, sB + wn * 32 + j * 16, 72);
            wmma::mma_sync(c[j], af, bf, c[j]);
        }
    }

    for (int ph = 0; ph < 4; ph++) {
        __syncthreads();
        if (wm == ph) {
            wmma::store_matrix_sync(sC + wn * 32,      c[0], 68, wmma::mem_row_major);
            wmma::store_matrix_sync(sC + wn * 32 + 16, c[1], 68, wmma::mem_row_major);
        }
        __syncthreads();
        int r = t >> 4, c0 = (t & 15) * 4;
        int n = m0 + ph * 16 + r;
        if (n < NNODES) {
            const float* src = sC + r * 68 + c0;
            uint2 st;
            __half2* p = (__half2*)&st;
            p[0] = __floats2half2_rn(src[0], src[1]);
            p[1] = __floats2half2_rn(src[2], src[3]);
            *(uint2*)(g_h2h + (size_t)n * HID + c0) = st;
        }
    }
}

// ---------------- layer 2 attention dots -------------------------------------
// warp per node; lane l owns channels 2l, 2l+1
__global__ void k_dots2(const float* __restrict__ att_s, const float* __restrict__ att_d) {
    int t = threadIdx.x;    // 256
    int wid = t >> 5, l = t & 31;
    int n = blockIdx.x * 8 + wid;
    if (n >= NNODES) return;
    float2 v = __half22float2(*(const __half2*)(g_h2h + (size_t)n * HID + 2 * l));
    float ps = v.x * att_s[2 * l] + v.y * att_s[2 * l + 1];
    float pd = v.x * att_d[2 * l] + v.y * att_d[2 * l + 1];
#pragma unroll
    for (int s = 1; s <= 16; s <<= 1) {
        ps += __shfl_xor_sync(0xffffffffu, ps, s);
        pd += __shfl_xor_sync(0xffffffffu, pd, s);
    }
    if (l == 0) {
        g_as2[n] = ps;
        g_ad2[n] = pd;
    }
}

// ---------------- layer 2 aggregation + bias/ELU + MLP head -----------------
__global__ void k_agg2(const float* __restrict__ b2,
                       const float* __restrict__ Wm1, const float* __restrict__ bm1,
                       const float* __restrict__ Wm2, const float* __restrict__ bm2,
                       float* __restrict__ out) {
    __shared__ float sh[4][HID];
    int wid = threadIdx.x >> 5, l = threadIdx.x & 31;
    int d = blockIdx.x * 4 + wid;
    if (d >= NNODES) return;
    int grp = l >> 3, cl = l & 7;
    int ch = 8 * cl;

    float adst = g_ad2[d];
    float den = 0.f;
    float a[8] = {0.f, 0.f, 0.f, 0.f, 0.f, 0.f, 0.f, 0.f};
    if (grp == 0) {                        // self-loop counted once
        float w = __expf(lrelu(g_as2[d] + adst));
        den = w;
        uint4 raw = *(const uint4*)(g_h2h + (size_t)d * HID + ch);
        const __half2* hp = (const __half2*)&raw;
#pragma unroll
        for (int i = 0; i < 4; i++) {
            float2 v = __half22float2(hp[i]);
            a[2 * i]     = w * v.x;
            a[2 * i + 1] = w * v.y;
        }
    }

    int beg = g_rowptr[d], end = g_rowptr[d + 1];
#pragma unroll 2
    for (int j = beg + grp; j < end; j += 4) {
        int s = g_col[j];
        float ww = __expf(lrelu(g_as2[s] + adst));
        den += ww;
        uint4 raw = *(const uint4*)(g_h2h + (size_t)s * HID + ch);
        const __half2* hp = (const __half2*)&raw;
#pragma unroll
        for (int i = 0; i < 4; i++) {
            float2 v = __half22float2(hp[i]);
            a[2 * i]     = fmaf(ww, v.x, a[2 * i]);
            a[2 * i + 1] = fmaf(ww, v.y, a[2 * i + 1]);
        }
    }

#pragma unroll
    for (int m = 8; m <= 16; m <<= 1) {
        den += __shfl_xor_sync(0xffffffffu, den, m);
#pragma unroll
        for (int i = 0; i < 8; i++) a[i] += __shfl_xor_sync(0xffffffffu, a[i], m);
    }

    float inv = 1.f / den;
    if (grp == 0) {
#pragma unroll
        for (int i = 0; i < 8; i++) {
            float hv = a[i] * inv + b2[ch + i];
            hv = hv > 0.f ? hv : expm1f(hv);
            sh[wid][ch + i] = hv;
        }
    }
    __syncwarp();

    float acc = bm1[l];
#pragma unroll
    for (int k = 0; k < HID; k++) acc = fmaf(sh[wid][k], Wm1[k * 32 + l], acc);
    float hid = acc > 0.f ? acc : 0.f;

    float p0 = hid * Wm2[l * 2];
    float p1 = hid * Wm2[l * 2 + 1];
#pragma unroll
    for (int s = 16; s >= 1; s >>= 1) {
        p0 += __shfl_xor_sync(0xffffffffu, p0, s);
        p1 += __shfl_xor_sync(0xffffffffu, p1, s);
    }
    if (l == 0) {
        out[d * 2]     = p0 + bm2[0];
        out[d * 2 + 1] = p1 + bm2[1];
    }
}

// ---------------- launch ----------------------------------------------------
extern "C" void kernel_launch(void* const* d_in, const int* in_sizes, int n_in,
                              void* d_out, int out_size) {
    const float* x   = (const float*)d_in[0];
    const int*   ei  = (const int*)  d_in[1];   // [2, E] int32: row0=src, row1=dst
    const float* W1  = (const float*)d_in[2];
    const float* as1 = (const float*)d_in[3];
    const float* ad1 = (const float*)d_in[4];
    const float* b1  = (const float*)d_in[5];
    const float* W2  = (const float*)d_in[6];
    const float* as2 = (const float*)d_in[7];
    const float* ad2 = (const float*)d_in[8];
    const float* b2  = (const float*)d_in[9];
    const float* Wm1 = (const float*)d_in[10];
    const float* bm1 = (const float*)d_in[11];
    const float* Wm2 = (const float*)d_in[12];
    const float* bm2 = (const float*)d_in[13];
    float* out = (float*)d_out;

    const int* src = ei;
    const int* dst = ei + NEDGES;

    k_cvtx   <<<(NNODES * INF / 8 + 255) / 256, 256>>>(x);       // 0
    k_cvtw   <<<(INF * C1 + 255) / 256, 256>>>(W1, W2);          // 1
    k_hist   <<<(NEDGES + 255) / 256, 256>>>(dst);               // 2
    k_gemm1  <<<(NNODES + 63) / 64, 256>>>();                    // 3 <- profiled
    k_scan1  <<<49, 1024>>>();                                   // 4
    k_scan23 <<<49, 1024>>>();                                   // 5
    k_dots1  <<<(NNODES + 7) / 8, 256>>>(as1, ad1);              // 6
    k_scatter<<<(NEDGES + 255) / 256, 256>>>(src, dst);          // 7
    k_agg1   <<<(NNODES + 3) / 4, 128>>>(b1);                    // 8
    k_gemm2  <<<(NNODES + 63) / 64, 256>>>();                    // 9
    k_dots2  <<<(NNODES + 7) / 8, 256>>>(as2, ad2);              // 10
    k_agg2   <<<(NNODES + 3) / 4, 128>>>(b2, Wm1, bm1, Wm2, bm2, out);  // 11
}

// round 11
// speedup vs baseline: 1.6973x; 1.0578x over previous
#include <cuda_runtime.h>
#include <cuda_fp16.h>
#include <mma.h>
#include <math.h>

using namespace nvcuda;

#define NNODES 50000
#define NEDGES 800000
#define INF    128
#define HID    64
#define HEADS  4
#define C1     256   // HEADS*HID
#define NEG    0.2f

// ---------------- scratch (device globals; no runtime allocation) ----------
__device__ __half g_xh  [NNODES * INF]; // x in fp16
__device__ __half g_w1h [INF * C1];     // W1 fp16
__device__ __half g_w2h [C1 * HID];     // W2 fp16
__device__ __half g_h1h [NNODES * C1];  // layer1 pre-attention features (fp16)
__device__ __half g_h1eh[NNODES * C1];  // layer1 output (post bias+ELU), fp16
__device__ float  g_as1[NNODES * HEADS];
__device__ float  g_ad1[NNODES * HEADS];
__device__ __half g_h2h[NNODES * HID];  // layer2 pre-attention features (fp16)
__device__ float  g_as2[NNODES];
__device__ float  g_ad2[NNODES];
__device__ int    g_deg   [NNODES];
__device__ int    g_rowptr[NNODES + 1];
__device__ int    g_cursor[NNODES];
__device__ int    g_col   [NEDGES];
__device__ int    g_bsum  [64];

__device__ __forceinline__ float lrelu(float v) { return v > 0.f ? v : NEG * v; }

// ---------------- fp16 conversions ------------------------------------------
__global__ void k_cvtx(const float* __restrict__ x) {
    int i = blockIdx.x * blockDim.x + threadIdx.x;   // each thread: 8 floats
    size_t o = (size_t)i * 8;
    if (o < (size_t)NNODES * INF) {
        float4 v0 = *(const float4*)(x + o);
        float4 v1 = *(const float4*)(x + o + 4);
        uint4 st;
        __half2* p = (__half2*)&st;
        p[0] = __floats2half2_rn(v0.x, v0.y);
        p[1] = __floats2half2_rn(v0.z, v0.w);
        p[2] = __floats2half2_rn(v1.x, v1.y);
        p[3] = __floats2half2_rn(v1.z, v1.w);
        *(uint4*)(g_xh + o) = st;
    }
}

__global__ void k_cvtw(const float* __restrict__ W1, const float* __restrict__ W2) {
    int i = blockIdx.x * blockDim.x + threadIdx.x;   // 32768 threads
    if (i < INF * C1)  g_w1h[i] = __float2half_rn(W1[i]);
    if (i < C1 * HID)  g_w2h[i] = __float2half_rn(W2[i]);
}

// ---------------- CSR construction ------------------------------------------
__global__ void k_hist(const int* __restrict__ dst) {
    int i = blockIdx.x * blockDim.x + threadIdx.x;
    if (i < NEDGES) atomicAdd(&g_deg[dst[i]], 1);
}

__global__ void k_scan1() {
    __shared__ int sh[1024];
    int tid = threadIdx.x;
    int i = blockIdx.x * 1024 + tid;
    int v = (i < NNODES) ? g_deg[i] : 0;
    sh[tid] = v;
    __syncthreads();
    for (int s = 1; s < 1024; s <<= 1) {
        int t = (tid >= s) ? sh[tid - s] : 0;
        __syncthreads();
        sh[tid] += t;
        __syncthreads();
    }
    if (i < NNODES) g_rowptr[i] = sh[tid] - v;
    if (tid == 1023) g_bsum[blockIdx.x] = sh[1023];
}

// apply per-block offset, init cursor, zero g_deg for next replay
__global__ void k_scan23() {
    __shared__ int soff;
    int tid = threadIdx.x;
    int bid = blockIdx.x;
    if (tid < 32) {
        int v = 0;
        if (tid < bid && tid < 49) v += g_bsum[tid];
        int t2 = tid + 32;
        if (t2 < bid && t2 < 49) v += g_bsum[t2];
#pragma unroll
        for (int s = 16; s >= 1; s >>= 1) v += __shfl_xor_sync(0xffffffffu, v, s);
        if (tid == 0) soff = v;
    }
    __syncthreads();
    int i = bid * 1024 + tid;
    if (i < NNODES) {
        int r = g_rowptr[i] + soff;
        g_rowptr[i] = r;
        g_cursor[i] = r;
        g_deg[i] = 0;
    }
    if (i == 0) g_rowptr[NNODES] = NEDGES;
}

__global__ void k_scatter(const int* __restrict__ src, const int* __restrict__ dst) {
    int i = blockIdx.x * blockDim.x + threadIdx.x;
    if (i < NEDGES) {
        int p = atomicAdd(&g_cursor[dst[i]], 1);
        g_col[p] = src[i];
    }
}

// ---------------- layer 1 GEMM via wmma: 64 nodes x 256 ch per block --------
// Dynamic smem: sA 64x136 fp16, sB = ALL of W1 (128x264 fp16), sC 16x260 fp32.
// Zero syncthreads in the mainloop; dots fused into the epilogue.
#define SZ1 (64 * 136 * 2 + 128 * 264 * 2 + 16 * 260 * 4)   // 101632 B
__global__ void k_gemm1(const float* __restrict__ att_s, const float* __restrict__ att_d) {
    extern __shared__ __align__(16) char smem[];
    __half* sA = (__half*)smem;
    __half* sB = (__half*)(smem + 64 * 136 * 2);
    float*  sC = (float*)(smem + 64 * 136 * 2 + 128 * 264 * 2);
    int t = threadIdx.x;
    int w = t >> 5;
    int wm = w & 3, wn = w >> 2;
    int m0 = blockIdx.x * 64;

    // stage A: 64 rows x 128 fp16 (1024 uint4)
    for (int i = t; i < 1024; i += 256) {
        int r = i >> 4, q = i & 15;
        uint4 v = make_uint4(0, 0, 0, 0);
        if (m0 + r < NNODES) v = *(const uint4*)(g_xh + (size_t)(m0 + r) * INF + q * 8);
        *(uint4*)(sA + r * 136 + q * 8) = v;
    }
    // stage B: all of W1, 128 rows x 256 fp16 (4096 uint4)
    for (int i = t; i < 4096; i += 256) {
        int r = i >> 5, q = i & 31;
        *(uint4*)(sB + r * 264 + q * 8) = *(const uint4*)(g_w1h + (size_t)r * C1 + q * 8);
    }
    __syncthreads();

    wmma::fragment<wmma::accumulator, 16, 16, 16, float> c[8];
#pragma unroll
    for (int j = 0; j < 8; j++) wmma::fill_fragment(c[j], 0.f);

#pragma unroll
    for (int kk = 0; kk < 8; kk++) {
        wmma::fragment<wmma::matrix_a, 16, 16, 16, __half, wmma::row_major> af;
        wmma::load_matrix_sync(af, sA + wm * 16 * 136 + kk * 16, 136);
#pragma unroll
        for (int j = 0; j < 8; j++) {
            wmma::fragment<wmma::matrix_b, 16, 16, 16, __half, wmma::row_major> bf;
            wmma::load_matrix_sync(bf, sB + kk * 16 * 264 + wn * 128 + j * 16, 264);
            wmma::mma_sync(c[j], af, bf, c[j]);
        }
    }

    __syncthreads();                 // all warps done reading sB
    float* attS = (float*)sB;        // reuse B region for attention vectors
    float* attD = attS + C1;
    if (t < C1) { attS[t] = att_s[t]; attD[t] = att_d[t]; }

    // epilogue: 4 phases; fp16 feature store + fused attention dots
    for (int ph = 0; ph < 4; ph++) {
        __syncthreads();
        if (wm == ph) {
#pragma unroll
            for (int j = 0; j < 8; j++)
                wmma::store_matrix_sync(sC + wn * 128 + j * 16, c[j], 260, wmma::mem_row_major);
        }
        __syncthreads();
        int r = t >> 4, q = t & 15, c0 = q * 16;
        int n = m0 + ph * 16 + r;
        const float* src = sC + r * 260 + c0;
        if (n < NNODES) {
            uint4 st0, st1;
            __half2* p0 = (__half2*)&st0;
            __half2* p1 = (__half2*)&st1;
            p0[0] = __floats2half2_rn(src[0], src[1]);
            p0[1] = __floats2half2_rn(src[2], src[3]);
            p0[2] = __floats2half2_rn(src[4], src[5]);
            p0[3] = __floats2half2_rn(src[6], src[7]);
            p1[0] = __floats2half2_rn(src[8], src[9]);
            p1[1] = __floats2half2_rn(src[10], src[11]);
            p1[2] = __floats2half2_rn(src[12], src[13]);
            p1[3] = __floats2half2_rn(src[14], src[15]);
            *(uint4*)(g_h1h + (size_t)n * C1 + c0)     = st0;
            *(uint4*)(g_h1h + (size_t)n * C1 + c0 + 8) = st1;
        }
        float ps = 0.f, pd = 0.f;
#pragma unroll
        for (int i = 0; i < 16; i++) {
            float v = src[i];
            ps = fmaf(v, attS[c0 + i], ps);
            pd = fmaf(v, attD[c0 + i], pd);
        }
        // fold 4 threads of same head (q bits 0,1)
        ps += __shfl_xor_sync(0xffffffffu, ps, 1);
        pd += __shfl_xor_sync(0xffffffffu, pd, 1);
        ps += __shfl_xor_sync(0xffffffffu, ps, 2);
        pd += __shfl_xor_sync(0xffffffffu, pd, 2);
        if ((q & 3) == 0 && n < NNODES) {
            int h = q >> 2;
            g_as1[n * HEADS + h] = ps;
            g_ad1[n * HEADS + h] = pd;
        }
    }
}

// ---------------- layer 1: warp-per-destination softmax aggregation ---------
// scores |e| <~ 10 so exp() cannot overflow fp32; max-shift unnecessary.
__global__ void k_agg1(const float* __restrict__ b1) {
    int wid = threadIdx.x >> 5, l = threadIdx.x & 31;
    int d = blockIdx.x * 4 + wid;
    if (d >= NNODES) return;
    int h = l >> 3;
    int ch = 8 * l;

    float adst = g_ad1[d * HEADS + h];
    float w = __expf(lrelu(g_as1[d * HEADS + h] + adst));  // self-loop
    float den = w;
    float a[8];
    {
        uint4 raw = *(const uint4*)(g_h1h + (size_t)d * C1 + ch);
        const __half2* hp = (const __half2*)&raw;
#pragma unroll
        for (int i = 0; i < 4; i++) {
            float2 v = __half22float2(hp[i]);
            a[2 * i]     = w * v.x;
            a[2 * i + 1] = w * v.y;
        }
    }

    int beg = g_rowptr[d], end = g_rowptr[d + 1];
#pragma unroll 4
    for (int j = beg; j < end; j++) {
        int s = g_col[j];
        float ww = __expf(lrelu(g_as1[s * HEADS + h] + adst));
        den += ww;
        uint4 raw = *(const uint4*)(g_h1h + (size_t)s * C1 + ch);
        const __half2* hp = (const __half2*)&raw;
#pragma unroll
        for (int i = 0; i < 4; i++) {
            float2 v = __half22float2(hp[i]);
            a[2 * i]     = fmaf(ww, v.x, a[2 * i]);
            a[2 * i + 1] = fmaf(ww, v.y, a[2 * i + 1]);
        }
    }
    float inv = 1.f / den;
    float4 b0 = *(const float4*)(b1 + ch);
    float4 b4 = *(const float4*)(b1 + ch + 4);
    float o[8];
    o[0] = a[0] * inv + b0.x; o[1] = a[1] * inv + b0.y;
    o[2] = a[2] * inv + b0.z; o[3] = a[3] * inv + b0.w;
    o[4] = a[4] * inv + b4.x; o[5] = a[5] * inv + b4.y;
    o[6] = a[6] * inv + b4.z; o[7] = a[7] * inv + b4.w;
#pragma unroll
    for (int i = 0; i < 8; i++) o[i] = o[i] > 0.f ? o[i] : expm1f(o[i]);
    uint4 st;
    __half2* sp = (__half2*)&st;
    sp[0] = __floats2half2_rn(o[0], o[1]);
    sp[1] = __floats2half2_rn(o[2], o[3]);
    sp[2] = __floats2half2_rn(o[4], o[5]);
    sp[3] = __floats2half2_rn(o[6], o[7]);
    *(uint4*)(g_h1eh + (size_t)d * C1 + ch) = st;
}

// ---------------- layer 2 GEMM via wmma: 64 nodes x 64 ch per block ---------
// Dynamic smem: sA 64x264, sB = ALL of W2 (256x72), sC 16x68. No mainloop syncs.
#define SZ2 (64 * 264 * 2 + 256 * 72 * 2 + 16 * 68 * 4)   // 75008 B
__global__ void k_gemm2(const float* __restrict__ att_s, const float* __restrict__ att_d) {
    extern __shared__ __align__(16) char smem[];
    __half* sA = (__half*)smem;
    __half* sB = (__half*)(smem + 64 * 264 * 2);
    float*  sC = (float*)(smem + 64 * 264 * 2 + 256 * 72 * 2);
    int t = threadIdx.x;
    int w = t >> 5;
    int wm = w & 3, wn = w >> 2;
    int m0 = blockIdx.x * 64;

    // stage A: 64 rows x 256 fp16 (2048 uint4)
    for (int i = t; i < 2048; i += 256) {
        int r = i >> 5, q = i & 31;
        uint4 v = make_uint4(0, 0, 0, 0);
        if (m0 + r < NNODES) v = *(const uint4*)(g_h1eh + (size_t)(m0 + r) * C1 + q * 8);
        *(uint4*)(sA + r * 264 + q * 8) = v;
    }
    // stage B: all of W2, 256 rows x 64 fp16 (2048 uint4)
    for (int i = t; i < 2048; i += 256) {
        int r = i >> 3, q = i & 7;
        *(uint4*)(sB + r * 72 + q * 8) = *(const uint4*)(g_w2h + (size_t)r * HID + q * 8);
    }
    __syncthreads();

    wmma::fragment<wmma::accumulator, 16, 16, 16, float> c[2];
    wmma::fill_fragment(c[0], 0.f);
    wmma::fill_fragment(c[1], 0.f);

#pragma unroll
    for (int kk = 0; kk < 16; kk++) {
        wmma::fragment<wmma::matrix_a, 16, 16, 16, __half, wmma::row_major> af;
        wmma::load_matrix_sync(af, sA + wm * 16 * 264 + kk * 16, 264);
#pragma unroll
        for (int j = 0; j < 2; j++) {
            wmma::fragment<wmma::matrix_b, 16, 16, 16, __half, wmma::row_major> bf;
            wmma::load_matrix_sync(bf, sB + kk * 16 * 72 + wn * 32 + j * 16, 72);
            wmma::mma_sync(c[j], af, bf, c[j]);
        }
    }

    __syncthreads();
    float* attS = (float*)sB;
    float* attD = attS + HID;
    if (t < HID) { attS[t] = att_s[t]; attD[t] = att_d[t]; }

    for (int ph = 0; ph < 4; ph++) {
        __syncthreads();
        if (wm == ph) {
            wmma::store_matrix_sync(sC + wn * 32,      c[0], 68, wmma::mem_row_major);
            wmma::store_matrix_sync(sC + wn * 32 + 16, c[1], 68, wmma::mem_row_major);
        }
        __syncthreads();
        int r = t >> 4, q = t & 15, c0 = q * 4;
        int n = m0 + ph * 16 + r;
        const float* src = sC + r * 68 + c0;
        if (n < NNODES) {
            uint2 st;
            __half2* p = (__half2*)&st;
            p[0] = __floats2half2_rn(src[0], src[1]);
            p[1] = __floats2half2_rn(src[2], src[3]);
            *(uint2*)(g_h2h + (size_t)n * HID + c0) = st;
        }
        float ps = 0.f, pd = 0.f;
#pragma unroll
        for (int i = 0; i < 4; i++) {
            float v = src[i];
            ps = fmaf(v, attS[c0 + i], ps);
            pd = fmaf(v, attD[c0 + i], pd);
        }
#pragma unroll
        for (int s = 1; s <= 8; s <<= 1) {
            ps += __shfl_xor_sync(0xffffffffu, ps, s);
            pd += __shfl_xor_sync(0xffffffffu, pd, s);
        }
        if (q == 0 && n < NNODES) {
            g_as2[n] = ps;
            g_ad2[n] = pd;
        }
    }
}

// ---------------- layer 2 aggregation + bias/ELU + MLP head -----------------
__global__ void k_agg2(const float* __restrict__ b2,
                       const float* __restrict__ Wm1, const float* __restrict__ bm1,
                       const float* __restrict__ Wm2, const float* __restrict__ bm2,
                       float* __restrict__ out) {
    __shared__ float sh[4][HID];
    int wid = threadIdx.x >> 5, l = threadIdx.x & 31;
    int d = blockIdx.x * 4 + wid;
    if (d >= NNODES) return;
    int grp = l >> 3, cl = l & 7;
    int ch = 8 * cl;

    float adst = g_ad2[d];
    float den = 0.f;
    float a[8] = {0.f, 0.f, 0.f, 0.f, 0.f, 0.f, 0.f, 0.f};
    if (grp == 0) {                        // self-loop counted once
        float w = __expf(lrelu(g_as2[d] + adst));
        den = w;
        uint4 raw = *(const uint4*)(g_h2h + (size_t)d * HID + ch);
        const __half2* hp = (const __half2*)&raw;
#pragma unroll
        for (int i = 0; i < 4; i++) {
            float2 v = __half22float2(hp[i]);
            a[2 * i]     = w * v.x;
            a[2 * i + 1] = w * v.y;
        }
    }

    int beg = g_rowptr[d], end = g_rowptr[d + 1];
#pragma unroll 2
    for (int j = beg + grp; j < end; j += 4) {
        int s = g_col[j];
        float ww = __expf(lrelu(g_as2[s] + adst));
        den += ww;
        uint4 raw = *(const uint4*)(g_h2h + (size_t)s * HID + ch);
        const __half2* hp = (const __half2*)&raw;
#pragma unroll
        for (int i = 0; i < 4; i++) {
            float2 v = __half22float2(hp[i]);
            a[2 * i]     = fmaf(ww, v.x, a[2 * i]);
            a[2 * i + 1] = fmaf(ww, v.y, a[2 * i + 1]);
        }
    }

#pragma unroll
    for (int m = 8; m <= 16; m <<= 1) {
        den += __shfl_xor_sync(0xffffffffu, den, m);
#pragma unroll
        for (int i = 0; i < 8; i++) a[i] += __shfl_xor_sync(0xffffffffu, a[i], m);
    }

    float inv = 1.f / den;
    if (grp == 0) {
#pragma unroll
        for (int i = 0; i < 8; i++) {
            float hv = a[i] * inv + b2[ch + i];
            hv = hv > 0.f ? hv : expm1f(hv);
            sh[wid][ch + i] = hv;
        }
    }
    __syncwarp();

    float acc = bm1[l];
#pragma unroll
    for (int k = 0; k < HID; k++) acc = fmaf(sh[wid][k], Wm1[k * 32 + l], acc);
    float hid = acc > 0.f ? acc : 0.f;

    float p0 = hid * Wm2[l * 2];
    float p1 = hid * Wm2[l * 2 + 1];
#pragma unroll
    for (int s = 16; s >= 1; s >>= 1) {
        p0 += __shfl_xor_sync(0xffffffffu, p0, s);
        p1 += __shfl_xor_sync(0xffffffffu, p1, s);
    }
    if (l == 0) {
        out[d * 2]     = p0 + bm2[0];
        out[d * 2 + 1] = p1 + bm2[1];
    }
}

// ---------------- launch ----------------------------------------------------
extern "C" void kernel_launch(void* const* d_in, const int* in_sizes, int n_in,
                              void* d_out, int out_size) {
    const float* x   = (const float*)d_in[0];
    const int*   ei  = (const int*)  d_in[1];   // [2, E] int32: row0=src, row1=dst
    const float* W1  = (const float*)d_in[2];
    const float* as1 = (const float*)d_in[3];
    const float* ad1 = (const float*)d_in[4];
    const float* b1  = (const float*)d_in[5];
    const float* W2  = (const float*)d_in[6];
    const float* as2 = (const float*)d_in[7];
    const float* ad2 = (const float*)d_in[8];
    const float* b2  = (const float*)d_in[9];
    const float* Wm1 = (const float*)d_in[10];
    const float* bm1 = (const float*)d_in[11];
    const float* Wm2 = (const float*)d_in[12];
    const float* bm2 = (const float*)d_in[13];
    float* out = (float*)d_out;

    const int* src = ei;
    const int* dst = ei + NEDGES;

    cudaFuncSetAttribute(k_gemm1, cudaFuncAttributeMaxDynamicSharedMemorySize, SZ1);
    cudaFuncSetAttribute(k_gemm2, cudaFuncAttributeMaxDynamicSharedMemorySize, SZ2);

    k_cvtx   <<<(NNODES * INF / 8 + 255) / 256, 256>>>(x);       // 0
    k_cvtw   <<<(INF * C1 + 255) / 256, 256>>>(W1, W2);          // 1
    k_hist   <<<(NEDGES + 255) / 256, 256>>>(dst);               // 2
    k_gemm1  <<<(NNODES + 63) / 64, 256, SZ1>>>(as1, ad1);       // 3 <- profiled
    k_scan1  <<<49, 1024>>>();                                   // 4
    k_scan23 <<<49, 1024>>>();                                   // 5
    k_scatter<<<(NEDGES + 255) / 256, 256>>>(src, dst);          // 6
    k_agg1   <<<(NNODES + 3) / 4, 128>>>(b1);                    // 7
    k_gemm2  <<<(NNODES + 63) / 64, 256, SZ2>>>(as2, ad2);       // 8
    k_agg2   <<<(NNODES + 3) / 4, 128>>>(b2, Wm1, bm1, Wm2, bm2, out);  // 9
}

// round 12
// speedup vs baseline: 1.8807x; 1.1080x over previous
#include <cuda_runtime.h>
#include <cuda_fp16.h>
#include <mma.h>
#include <math.h>

using namespace nvcuda;

#define NNODES 50000
#define NEDGES 800000
#define INF    128
#define HID    64
#define HEADS  4
#define C1     256   // HEADS*HID
#define NEG    0.2f

// ---------------- scratch (device globals; no runtime allocation) ----------
__device__ __half g_w1h [INF * C1];     // W1 fp16
__device__ __half g_w2h [C1 * HID];     // W2 fp16
__device__ __half g_h1h [NNODES * C1];  // layer1 pre-attention features (fp16)
__device__ __half g_h1eh[NNODES * C1];  // layer1 output (post bias+ELU), fp16
__device__ float  g_as1[NNODES * HEADS];
__device__ float  g_ad1[NNODES * HEADS];
__device__ __half g_h2h[NNODES * HID];  // layer2 pre-attention features (fp16)
__device__ float  g_as2[NNODES];
__device__ float  g_ad2[NNODES];
__device__ int    g_deg   [NNODES];
__device__ int    g_rowptr[NNODES + 1];
__device__ int    g_cursor[NNODES];
__device__ int    g_col   [NEDGES];
__device__ int    g_bsum  [64];

__device__ __forceinline__ float lrelu(float v) { return v > 0.f ? v : NEG * v; }

// ---------------- fp16 weight conversion -------------------------------------
__global__ void k_cvtw(const float* __restrict__ W1, const float* __restrict__ W2) {
    int i = blockIdx.x * blockDim.x + threadIdx.x;   // 32768 threads
    if (i < INF * C1)  g_w1h[i] = __float2half_rn(W1[i]);
    if (i < C1 * HID)  g_w2h[i] = __float2half_rn(W2[i]);
}

// ---------------- CSR construction ------------------------------------------
__global__ void k_hist(const int* __restrict__ dst) {
    int i = blockIdx.x * blockDim.x + threadIdx.x;
    if (i < NEDGES) atomicAdd(&g_deg[dst[i]], 1);
}

__global__ void k_scan1() {
    __shared__ int sh[1024];
    int tid = threadIdx.x;
    int i = blockIdx.x * 1024 + tid;
    int v = (i < NNODES) ? g_deg[i] : 0;
    sh[tid] = v;
    __syncthreads();
    for (int s = 1; s < 1024; s <<= 1) {
        int t = (tid >= s) ? sh[tid - s] : 0;
        __syncthreads();
        sh[tid] += t;
        __syncthreads();
    }
    if (i < NNODES) g_rowptr[i] = sh[tid] - v;
    if (tid == 1023) g_bsum[blockIdx.x] = sh[1023];
}

// apply per-block offset, init cursor, zero g_deg for next replay
__global__ void k_scan23() {
    __shared__ int soff;
    int tid = threadIdx.x;
    int bid = blockIdx.x;
    if (tid < 32) {
        int v = 0;
        if (tid < bid && tid < 49) v += g_bsum[tid];
        int t2 = tid + 32;
        if (t2 < bid && t2 < 49) v += g_bsum[t2];
#pragma unroll
        for (int s = 16; s >= 1; s >>= 1) v += __shfl_xor_sync(0xffffffffu, v, s);
        if (tid == 0) soff = v;
    }
    __syncthreads();
    int i = bid * 1024 + tid;
    if (i < NNODES) {
        int r = g_rowptr[i] + soff;
        g_rowptr[i] = r;
        g_cursor[i] = r;
        g_deg[i] = 0;
    }
    if (i == 0) g_rowptr[NNODES] = NEDGES;
}

__global__ void k_scatter(const int* __restrict__ src, const int* __restrict__ dst) {
    int i = blockIdx.x * blockDim.x + threadIdx.x;
    if (i < NEDGES) {
        int p = atomicAdd(&g_cursor[dst[i]], 1);
        g_col[p] = src[i];
    }
}

// ---------------- layer 1 GEMM via wmma: 64 nodes x 256 ch per block --------
// 512 threads = 16 warps (4m x 4n); warp tile 16 x 64 (4 accum frags).
// x fp32->fp16 conversion fused into A staging. Whole W1 resident in smem.
#define SZ1 (64 * 136 * 2 + 128 * 264 * 2 + 16 * 260 * 4)   // 101632 B
__global__ void __launch_bounds__(512, 2)
k_gemm1(const float* __restrict__ x,
        const float* __restrict__ att_s, const float* __restrict__ att_d) {
    extern __shared__ __align__(16) char smem[];
    __half* sA = (__half*)smem;
    __half* sB = (__half*)(smem + 64 * 136 * 2);
    float*  sC = (float*)(smem + 64 * 136 * 2 + 128 * 264 * 2);
    int t = threadIdx.x;
    int w = t >> 5;
    int wm = w >> 2, wn = w & 3;
    int m0 = blockIdx.x * 64;

    // stage A with fused fp32->fp16: 64 rows x 128 ch (1024 jobs of 8 halves)
    for (int i = t; i < 1024; i += 512) {
        int r = i >> 4, q = i & 15;
        int n = m0 + r;
        uint4 st = make_uint4(0, 0, 0, 0);
        if (n < NNODES) {
            const float4* xp = (const float4*)(x + (size_t)n * INF + q * 8);
            float4 v0 = xp[0], v1 = xp[1];
            __half2* p = (__half2*)&st;
            p[0] = __floats2half2_rn(v0.x, v0.y);
            p[1] = __floats2half2_rn(v0.z, v0.w);
            p[2] = __floats2half2_rn(v1.x, v1.y);
            p[3] = __floats2half2_rn(v1.z, v1.w);
        }
        *(uint4*)(sA + r * 136 + q * 8) = st;
    }
    // stage B: all of W1, 128 rows x 256 fp16 (4096 uint4)
    for (int i = t; i < 4096; i += 512) {
        int r = i >> 5, q = i & 31;
        *(uint4*)(sB + r * 264 + q * 8) = *(const uint4*)(g_w1h + (size_t)r * C1 + q * 8);
    }
    __syncthreads();

    wmma::fragment<wmma::accumulator, 16, 16, 16, float> c[4];
#pragma unroll
    for (int j = 0; j < 4; j++) wmma::fill_fragment(c[j], 0.f);

#pragma unroll
    for (int kk = 0; kk < 8; kk++) {
        wmma::fragment<wmma::matrix_a, 16, 16, 16, __half, wmma::row_major> af;
        wmma::load_matrix_sync(af, sA + wm * 16 * 136 + kk * 16, 136);
#pragma unroll
        for (int j = 0; j < 4; j++) {
            wmma::fragment<wmma::matrix_b, 16, 16, 16, __half, wmma::row_major> bf;
            wmma::load_matrix_sync(bf, sB + kk * 16 * 264 + wn * 64 + j * 16, 264);
            wmma::mma_sync(c[j], af, bf, c[j]);
        }
    }

    __syncthreads();                 // all warps done reading sB
    float* attS = (float*)sB;        // reuse B region for attention vectors
    float* attD = attS + C1;
    if (t < C1) attS[t] = att_s[t];
    else if (t < 2 * C1) attD[t - C1] = att_d[t - C1];

    // epilogue: 4 phases (one 16-row m-tile through sC); fused dots
    for (int ph = 0; ph < 4; ph++) {
        __syncthreads();
        if (wm == ph) {
#pragma unroll
            for (int j = 0; j < 4; j++)
                wmma::store_matrix_sync(sC + wn * 64 + j * 16, c[j], 260, wmma::mem_row_major);
        }
        __syncthreads();
        int r = t >> 5, q = t & 31, c0 = q * 8;   // warp = one row; 8 cols/thread
        int n = m0 + ph * 16 + r;
        const float* src = sC + r * 260 + c0;
        if (n < NNODES) {
            uint4 st;
            __half2* p = (__half2*)&st;
            p[0] = __floats2half2_rn(src[0], src[1]);
            p[1] = __floats2half2_rn(src[2], src[3]);
            p[2] = __floats2half2_rn(src[4], src[5]);
            p[3] = __floats2half2_rn(src[6], src[7]);
            *(uint4*)(g_h1h + (size_t)n * C1 + c0) = st;
        }
        float ps = 0.f, pd = 0.f;
#pragma unroll
        for (int i = 0; i < 8; i++) {
            float v = src[i];
            ps = fmaf(v, attS[c0 + i], ps);
            pd = fmaf(v, attD[c0 + i], pd);
        }
        // fold 8 threads of same head (bits 0..2 of lane)
#pragma unroll
        for (int s = 1; s <= 4; s <<= 1) {
            ps += __shfl_xor_sync(0xffffffffu, ps, s);
            pd += __shfl_xor_sync(0xffffffffu, pd, s);
        }
        if ((q & 7) == 0 && n < NNODES) {
            int h = q >> 3;
            g_as1[n * HEADS + h] = ps;
            g_ad1[n * HEADS + h] = pd;
        }
    }
}

// ---------------- layer 1: warp-per-destination softmax aggregation ---------
// scores |e| <~ 10 so exp() cannot overflow fp32; max-shift unnecessary.
__global__ void k_agg1(const float* __restrict__ b1) {
    int wid = threadIdx.x >> 5, l = threadIdx.x & 31;
    int d = blockIdx.x * 4 + wid;
    if (d >= NNODES) return;
    int h = l >> 3;
    int ch = 8 * l;

    float adst = g_ad1[d * HEADS + h];
    float w = __expf(lrelu(g_as1[d * HEADS + h] + adst));  // self-loop
    float den = w;
    float a[8];
    {
        uint4 raw = *(const uint4*)(g_h1h + (size_t)d * C1 + ch);
        const __half2* hp = (const __half2*)&raw;
#pragma unroll
        for (int i = 0; i < 4; i++) {
            float2 v = __half22float2(hp[i]);
            a[2 * i]     = w * v.x;
            a[2 * i + 1] = w * v.y;
        }
    }

    int beg = g_rowptr[d], end = g_rowptr[d + 1];
#pragma unroll 4
    for (int j = beg; j < end; j++) {
        int s = g_col[j];
        float ww = __expf(lrelu(g_as1[s * HEADS + h] + adst));
        den += ww;
        uint4 raw = *(const uint4*)(g_h1h + (size_t)s * C1 + ch);
        const __half2* hp = (const __half2*)&raw;
#pragma unroll
        for (int i = 0; i < 4; i++) {
            float2 v = __half22float2(hp[i]);
            a[2 * i]     = fmaf(ww, v.x, a[2 * i]);
            a[2 * i + 1] = fmaf(ww, v.y, a[2 * i + 1]);
        }
    }
    float inv = 1.f / den;
    float4 b0 = *(const float4*)(b1 + ch);
    float4 b4 = *(const float4*)(b1 + ch + 4);
    float o[8];
    o[0] = a[0] * inv + b0.x; o[1] = a[1] * inv + b0.y;
    o[2] = a[2] * inv + b0.z; o[3] = a[3] * inv + b0.w;
    o[4] = a[4] * inv + b4.x; o[5] = a[5] * inv + b4.y;
    o[6] = a[6] * inv + b4.z; o[7] = a[7] * inv + b4.w;
#pragma unroll
    for (int i = 0; i < 8; i++) o[i] = o[i] > 0.f ? o[i] : expm1f(o[i]);
    uint4 st;
    __half2* sp = (__half2*)&st;
    sp[0] = __floats2half2_rn(o[0], o[1]);
    sp[1] = __floats2half2_rn(o[2], o[3]);
    sp[2] = __floats2half2_rn(o[4], o[5]);
    sp[3] = __floats2half2_rn(o[6], o[7]);
    *(uint4*)(g_h1eh + (size_t)d * C1 + ch) = st;
}

// ---------------- layer 2 GEMM via wmma: 64 nodes x 64 ch per block ---------
// 512 threads = 16 warps (4m x 4n); warp tile 16 x 16 (1 accum frag).
#define SZ2 (64 * 264 * 2 + 256 * 72 * 2 + 16 * 68 * 4)   // 75008 B
__global__ void __launch_bounds__(512, 2)
k_gemm2(const float* __restrict__ att_s, const float* __restrict__ att_d) {
    extern __shared__ __align__(16) char smem[];
    __half* sA = (__half*)smem;
    __half* sB = (__half*)(smem + 64 * 264 * 2);
    float*  sC = (float*)(smem + 64 * 264 * 2 + 256 * 72 * 2);
    int t = threadIdx.x;
    int w = t >> 5;
    int wm = w >> 2, wn = w & 3;
    int m0 = blockIdx.x * 64;

    // stage A: 64 rows x 256 fp16 (2048 uint4)
    for (int i = t; i < 2048; i += 512) {
        int r = i >> 5, q = i & 31;
        uint4 v = make_uint4(0, 0, 0, 0);
        if (m0 + r < NNODES) v = *(const uint4*)(g_h1eh + (size_t)(m0 + r) * C1 + q * 8);
        *(uint4*)(sA + r * 264 + q * 8) = v;
    }
    // stage B: all of W2, 256 rows x 64 fp16 (2048 uint4)
    for (int i = t; i < 2048; i += 512) {
        int r = i >> 3, q = i & 7;
        *(uint4*)(sB + r * 72 + q * 8) = *(const uint4*)(g_w2h + (size_t)r * HID + q * 8);
    }
    __syncthreads();

    wmma::fragment<wmma::accumulator, 16, 16, 16, float> c;
    wmma::fill_fragment(c, 0.f);

#pragma unroll
    for (int kk = 0; kk < 16; kk++) {
        wmma::fragment<wmma::matrix_a, 16, 16, 16, __half, wmma::row_major> af;
        wmma::load_matrix_sync(af, sA + wm * 16 * 264 + kk * 16, 264);
        wmma::fragment<wmma::matrix_b, 16, 16, 16, __half, wmma::row_major> bf;
        wmma::load_matrix_sync(bf, sB + kk * 16 * 72 + wn * 16, 72);
        wmma::mma_sync(c, af, bf, c);
    }

    __syncthreads();
    float* attS = (float*)sB;
    float* attD = attS + HID;
    if (t < HID) attS[t] = att_s[t];
    else if (t < 2 * HID) attD[t - HID] = att_d[t - HID];

    for (int ph = 0; ph < 4; ph++) {
        __syncthreads();
        if (wm == ph)
            wmma::store_matrix_sync(sC + wn * 16, c, 68, wmma::mem_row_major);
        __syncthreads();
        int r = t >> 5, q = t & 31, c0 = q * 2;   // warp = one row; 2 cols/thread
        int n = m0 + ph * 16 + r;
        const float* src = sC + r * 68 + c0;
        if (n < NNODES)
            *(__half2*)(g_h2h + (size_t)n * HID + c0) = __floats2half2_rn(src[0], src[1]);
        float ps = src[0] * attS[c0] + src[1] * attS[c0 + 1];
        float pd = src[0] * attD[c0] + src[1] * attD[c0 + 1];
#pragma unroll
        for (int s = 1; s <= 16; s <<= 1) {
            ps += __shfl_xor_sync(0xffffffffu, ps, s);
            pd += __shfl_xor_sync(0xffffffffu, pd, s);
        }
        if (q == 0 && n < NNODES) {
            g_as2[n] = ps;
            g_ad2[n] = pd;
        }
    }
}

// ---------------- layer 2 aggregation + bias/ELU + MLP head -----------------
__global__ void k_agg2(const float* __restrict__ b2,
                       const float* __restrict__ Wm1, const float* __restrict__ bm1,
                       const float* __restrict__ Wm2, const float* __restrict__ bm2,
                       float* __restrict__ out) {
    __shared__ float sh[4][HID];
    int wid = threadIdx.x >> 5, l = threadIdx.x & 31;
    int d = blockIdx.x * 4 + wid;
    if (d >= NNODES) return;
    int grp = l >> 3, cl = l & 7;
    int ch = 8 * cl;

    float adst = g_ad2[d];
    float den = 0.f;
    float a[8] = {0.f, 0.f, 0.f, 0.f, 0.f, 0.f, 0.f, 0.f};
    if (grp == 0) {                        // self-loop counted once
        float w = __expf(lrelu(g_as2[d] + adst));
        den = w;
        uint4 raw = *(const uint4*)(g_h2h + (size_t)d * HID + ch);
        const __half2* hp = (const __half2*)&raw;
#pragma unroll
        for (int i = 0; i < 4; i++) {
            float2 v = __half22float2(hp[i]);
            a[2 * i]     = w * v.x;
            a[2 * i + 1] = w * v.y;
        }
    }

    int beg = g_rowptr[d], end = g_rowptr[d + 1];
#pragma unroll 2
    for (int j = beg + grp; j < end; j += 4) {
        int s = g_col[j];
        float ww = __expf(lrelu(g_as2[s] + adst));
        den += ww;
        uint4 raw = *(const uint4*)(g_h2h + (size_t)s * HID + ch);
        const __half2* hp = (const __half2*)&raw;
#pragma unroll
        for (int i = 0; i < 4; i++) {
            float2 v = __half22float2(hp[i]);
            a[2 * i]     = fmaf(ww, v.x, a[2 * i]);
            a[2 * i + 1] = fmaf(ww, v.y, a[2 * i + 1]);
        }
    }

#pragma unroll
    for (int m = 8; m <= 16; m <<= 1) {
        den += __shfl_xor_sync(0xffffffffu, den, m);
#pragma unroll
        for (int i = 0; i < 8; i++) a[i] += __shfl_xor_sync(0xffffffffu, a[i], m);
    }

    float inv = 1.f / den;
    if (grp == 0) {
#pragma unroll
        for (int i = 0; i < 8; i++) {
            float hv = a[i] * inv + b2[ch + i];
            hv = hv > 0.f ? hv : expm1f(hv);
            sh[wid][ch + i] = hv;
        }
    }
    __syncwarp();

    float acc = bm1[l];
#pragma unroll
    for (int k = 0; k < HID; k++) acc = fmaf(sh[wid][k], Wm1[k * 32 + l], acc);
    float hid = acc > 0.f ? acc : 0.f;

    float p0 = hid * Wm2[l * 2];
    float p1 = hid * Wm2[l * 2 + 1];
#pragma unroll
    for (int s = 16; s >= 1; s >>= 1) {
        p0 += __shfl_xor_sync(0xffffffffu, p0, s);
        p1 += __shfl_xor_sync(0xffffffffu, p1, s);
    }
    if (l == 0) {
        out[d * 2]     = p0 + bm2[0];
        out[d * 2 + 1] = p1 + bm2[1];
    }
}

// ---------------- launch ----------------------------------------------------
extern "C" void kernel_launch(void* const* d_in, const int* in_sizes, int n_in,
                              void* d_out, int out_size) {
    const float* x   = (const float*)d_in[0];
    const int*   ei  = (const int*)  d_in[1];   // [2, E] int32: row0=src, row1=dst
    const float* W1  = (const float*)d_in[2];
    const float* as1 = (const float*)d_in[3];
    const float* ad1 = (const float*)d_in[4];
    const float* b1  = (const float*)d_in[5];
    const float* W2  = (const float*)d_in[6];
    const float* as2 = (const float*)d_in[7];
    const float* ad2 = (const float*)d_in[8];
    const float* b2  = (const float*)d_in[9];
    const float* Wm1 = (const float*)d_in[10];
    const float* bm1 = (const float*)d_in[11];
    const float* Wm2 = (const float*)d_in[12];
    const float* bm2 = (const float*)d_in[13];
    float* out = (float*)d_out;

    const int* src = ei;
    const int* dst = ei + NEDGES;

    cudaFuncSetAttribute(k_gemm1, cudaFuncAttributeMaxDynamicSharedMemorySize, SZ1);
    cudaFuncSetAttribute(k_gemm2, cudaFuncAttributeMaxDynamicSharedMemorySize, SZ2);

    k_cvtw   <<<(INF * C1 + 255) / 256, 256>>>(W1, W2);          // 0
    k_hist   <<<(NEDGES + 255) / 256, 256>>>(dst);               // 1
    k_scan1  <<<49, 1024>>>();                                   // 2
    k_gemm1  <<<(NNODES + 63) / 64, 512, SZ1>>>(x, as1, ad1);    // 3 <- profiled
    k_scan23 <<<49, 1024>>>();                                   // 4
    k_scatter<<<(NEDGES + 255) / 256, 256>>>(src, dst);          // 5
    k_agg1   <<<(NNODES + 3) / 4, 128>>>(b1);                    // 6
    k_gemm2  <<<(NNODES + 63) / 64, 512, SZ2>>>(as2, ad2);       // 7
    k_agg2   <<<(NNODES + 3) / 4, 128>>>(b2, Wm1, bm1, Wm2, bm2, out);  // 8
}

// round 13
// speedup vs baseline: 1.9211x; 1.0215x over previous
#include <cuda_runtime.h>
#include <cuda_fp16.h>
#include <mma.h>
#include <math.h>

using namespace nvcuda;

#define NNODES 50000
#define NEDGES 800000
#define INF    128
#define HID    64
#define HEADS  4
#define C1     256   // HEADS*HID
#define NEG    0.2f

// ---------------- scratch (device globals; no runtime allocation) ----------
__device__ __half g_w1h [INF * C1];     // W1 fp16
__device__ __half g_w2h [C1 * HID];     // W2 fp16
__device__ __half g_h1h [NNODES * C1];  // layer1 pre-attention features (fp16)
__device__ __half g_h1eh[NNODES * C1];  // layer1 output (post bias+ELU), fp16
__device__ float  g_as1[NNODES * HEADS];
__device__ float  g_ad1[NNODES * HEADS];
__device__ __half g_h2h[NNODES * HID];  // layer2 pre-attention features (fp16)
__device__ float  g_as2[NNODES];
__device__ float  g_ad2[NNODES];
__device__ int    g_deg   [NNODES];
__device__ int    g_rowptr[NNODES + 1];
__device__ int    g_cursor[NNODES];
__device__ int    g_col   [NEDGES];
__device__ int    g_bsum  [64];

__device__ __forceinline__ float lrelu(float v) { return v > 0.f ? v : NEG * v; }

// ---------------- fp16 weight conversion -------------------------------------
__global__ void k_cvtw(const float* __restrict__ W1, const float* __restrict__ W2) {
    int i = blockIdx.x * blockDim.x + threadIdx.x;   // 32768 threads
    if (i < INF * C1)  g_w1h[i] = __float2half_rn(W1[i]);
    if (i < C1 * HID)  g_w2h[i] = __float2half_rn(W2[i]);
}

// ---------------- CSR construction ------------------------------------------
__global__ void k_hist(const int* __restrict__ dst) {
    int i = blockIdx.x * blockDim.x + threadIdx.x;
    if (i < NEDGES) atomicAdd(&g_deg[dst[i]], 1);
}

__global__ void k_scan1() {
    __shared__ int sh[1024];
    int tid = threadIdx.x;
    int i = blockIdx.x * 1024 + tid;
    int v = (i < NNODES) ? g_deg[i] : 0;
    sh[tid] = v;
    __syncthreads();
    for (int s = 1; s < 1024; s <<= 1) {
        int t = (tid >= s) ? sh[tid - s] : 0;
        __syncthreads();
        sh[tid] += t;
        __syncthreads();
    }
    if (i < NNODES) g_rowptr[i] = sh[tid] - v;
    if (tid == 1023) g_bsum[blockIdx.x] = sh[1023];
}

// apply per-block offset, init cursor, zero g_deg for next replay
__global__ void k_scan23() {
    __shared__ int soff;
    int tid = threadIdx.x;
    int bid = blockIdx.x;
    if (tid < 32) {
        int v = 0;
        if (tid < bid && tid < 49) v += g_bsum[tid];
        int t2 = tid + 32;
        if (t2 < bid && t2 < 49) v += g_bsum[t2];
#pragma unroll
        for (int s = 16; s >= 1; s >>= 1) v += __shfl_xor_sync(0xffffffffu, v, s);
        if (tid == 0) soff = v;
    }
    __syncthreads();
    int i = bid * 1024 + tid;
    if (i < NNODES) {
        int r = g_rowptr[i] + soff;
        g_rowptr[i] = r;
        g_cursor[i] = r;
        g_deg[i] = 0;
    }
    if (i == 0) g_rowptr[NNODES] = NEDGES;
}

__global__ void k_scatter(const int* __restrict__ src, const int* __restrict__ dst) {
    int i = blockIdx.x * blockDim.x + threadIdx.x;
    if (i < NEDGES) {
        int p = atomicAdd(&g_cursor[dst[i]], 1);
        g_col[p] = src[i];
    }
}

// ---------------- layer 1 GEMM via wmma: 64 nodes x 256 ch per block --------
// 512 threads = 16 warps (4m x 4n); warp tile 16 x 64 (4 accum frags).
// Single-phase epilogue: sC (64x260 fp32) aliases the DEAD sA/sB region.
// smem layout: mainloop  [0,17408) sA | [17408,84992) sB
//              epilogue  [0,66560) sC | [84992,87040) attS/attD
#define SZ1 87040
__global__ void __launch_bounds__(512, 2)
k_gemm1(const float* __restrict__ x,
        const float* __restrict__ att_s, const float* __restrict__ att_d) {
    extern __shared__ __align__(16) char smem[];
    __half* sA = (__half*)smem;
    __half* sB = (__half*)(smem + 17408);
    float*  sC = (float*)smem;                 // aliases sA+sB (dead after mainloop)
    float*  attS = (float*)(smem + 84992);
    float*  attD = attS + C1;
    int t = threadIdx.x;
    int w = t >> 5;
    int wm = w >> 2, wn = w & 3;
    int m0 = blockIdx.x * 64;

    // stage A with fused fp32->fp16: 64 rows x 128 ch
    for (int i = t; i < 1024; i += 512) {
        int r = i >> 4, q = i & 15;
        int n = m0 + r;
        uint4 st = make_uint4(0, 0, 0, 0);
        if (n < NNODES) {
            const float4* xp = (const float4*)(x + (size_t)n * INF + q * 8);
            float4 v0 = xp[0], v1 = xp[1];
            __half2* p = (__half2*)&st;
            p[0] = __floats2half2_rn(v0.x, v0.y);
            p[1] = __floats2half2_rn(v0.z, v0.w);
            p[2] = __floats2half2_rn(v1.x, v1.y);
            p[3] = __floats2half2_rn(v1.z, v1.w);
        }
        *(uint4*)(sA + r * 136 + q * 8) = st;
    }
    // stage B: all of W1, 128 rows x 256 fp16
    for (int i = t; i < 4096; i += 512) {
        int r = i >> 5, q = i & 31;
        *(uint4*)(sB + r * 264 + q * 8) = *(const uint4*)(g_w1h + (size_t)r * C1 + q * 8);
    }
    __syncthreads();

    wmma::fragment<wmma::accumulator, 16, 16, 16, float> c[4];
#pragma unroll
    for (int j = 0; j < 4; j++) wmma::fill_fragment(c[j], 0.f);

#pragma unroll
    for (int kk = 0; kk < 8; kk++) {
        wmma::fragment<wmma::matrix_a, 16, 16, 16, __half, wmma::row_major> af;
        wmma::load_matrix_sync(af, sA + wm * 16 * 136 + kk * 16, 136);
#pragma unroll
        for (int j = 0; j < 4; j++) {
            wmma::fragment<wmma::matrix_b, 16, 16, 16, __half, wmma::row_major> bf;
            wmma::load_matrix_sync(bf, sB + kk * 16 * 264 + wn * 64 + j * 16, 264);
            wmma::mma_sync(c[j], af, bf, c[j]);
        }
    }

    __syncthreads();                 // sA/sB dead; sC + att regions live
    if (t < C1) attS[t] = att_s[t];
    else if (t < 2 * C1) attD[t - C1] = att_d[t - C1];
    // ALL warps store their fragments concurrently
#pragma unroll
    for (int j = 0; j < 4; j++)
        wmma::store_matrix_sync(sC + (wm * 16) * 260 + wn * 64 + j * 16, c[j], 260,
                                wmma::mem_row_major);
    __syncthreads();

    // each thread: 4 rows x 8 cols; fp16 store + fused attention dots
    int r0 = t >> 5, q = t & 31, c0 = q * 8;
#pragma unroll
    for (int k = 0; k < 4; k++) {
        int r = r0 + k * 16;
        int n = m0 + r;
        const float* src = sC + r * 260 + c0;
        if (n < NNODES) {
            uint4 st;
            __half2* p = (__half2*)&st;
            p[0] = __floats2half2_rn(src[0], src[1]);
            p[1] = __floats2half2_rn(src[2], src[3]);
            p[2] = __floats2half2_rn(src[4], src[5]);
            p[3] = __floats2half2_rn(src[6], src[7]);
            *(uint4*)(g_h1h + (size_t)n * C1 + c0) = st;
        }
        float ps = 0.f, pd = 0.f;
#pragma unroll
        for (int i = 0; i < 8; i++) {
            float v = src[i];
            ps = fmaf(v, attS[c0 + i], ps);
            pd = fmaf(v, attD[c0 + i], pd);
        }
#pragma unroll
        for (int s = 1; s <= 4; s <<= 1) {
            ps += __shfl_xor_sync(0xffffffffu, ps, s);
            pd += __shfl_xor_sync(0xffffffffu, pd, s);
        }
        if ((q & 7) == 0 && n < NNODES) {
            int h = q >> 3;
            g_as1[n * HEADS + h] = ps;
            g_ad1[n * HEADS + h] = pd;
        }
    }
}

// ---------------- layer 1: warp-per-destination softmax aggregation ---------
// scores |e| <~ 10 so exp() cannot overflow fp32; max-shift unnecessary.
__global__ void k_agg1(const float* __restrict__ b1) {
    int wid = threadIdx.x >> 5, l = threadIdx.x & 31;
    int d = blockIdx.x * 4 + wid;
    if (d >= NNODES) return;
    int h = l >> 3;
    int ch = 8 * l;

    float adst = g_ad1[d * HEADS + h];
    float w = __expf(lrelu(g_as1[d * HEADS + h] + adst));  // self-loop
    float den = w;
    float a[8];
    {
        uint4 raw = *(const uint4*)(g_h1h + (size_t)d * C1 + ch);
        const __half2* hp = (const __half2*)&raw;
#pragma unroll
        for (int i = 0; i < 4; i++) {
            float2 v = __half22float2(hp[i]);
            a[2 * i]     = w * v.x;
            a[2 * i + 1] = w * v.y;
        }
    }

    int beg = g_rowptr[d], end = g_rowptr[d + 1];
#pragma unroll 4
    for (int j = beg; j < end; j++) {
        int s = g_col[j];
        float ww = __expf(lrelu(g_as1[s * HEADS + h] + adst));
        den += ww;
        uint4 raw = *(const uint4*)(g_h1h + (size_t)s * C1 + ch);
        const __half2* hp = (const __half2*)&raw;
#pragma unroll
        for (int i = 0; i < 4; i++) {
            float2 v = __half22float2(hp[i]);
            a[2 * i]     = fmaf(ww, v.x, a[2 * i]);
            a[2 * i + 1] = fmaf(ww, v.y, a[2 * i + 1]);
        }
    }
    float inv = 1.f / den;
    float4 b0 = *(const float4*)(b1 + ch);
    float4 b4 = *(const float4*)(b1 + ch + 4);
    float o[8];
    o[0] = a[0] * inv + b0.x; o[1] = a[1] * inv + b0.y;
    o[2] = a[2] * inv + b0.z; o[3] = a[3] * inv + b0.w;
    o[4] = a[4] * inv + b4.x; o[5] = a[5] * inv + b4.y;
    o[6] = a[6] * inv + b4.z; o[7] = a[7] * inv + b4.w;
#pragma unroll
    for (int i = 0; i < 8; i++) o[i] = o[i] > 0.f ? o[i] : expm1f(o[i]);
    uint4 st;
    __half2* sp = (__half2*)&st;
    sp[0] = __floats2half2_rn(o[0], o[1]);
    sp[1] = __floats2half2_rn(o[2], o[3]);
    sp[2] = __floats2half2_rn(o[4], o[5]);
    sp[3] = __floats2half2_rn(o[6], o[7]);
    *(uint4*)(g_h1eh + (size_t)d * C1 + ch) = st;
}

// ---------------- layer 2 GEMM via wmma: 64 nodes x 64 ch per block ---------
// 512 threads = 16 warps (4m x 4n); warp tile 16 x 16 (1 accum frag).
// Single-phase epilogue: sC (64x68 fp32) aliases dead sA.
// layout: mainloop [0,33792) sA | [33792,70656) sB
//         epilogue [0,17408) sC | [70656,71168) attS/attD
#define SZ2 71168
__global__ void __launch_bounds__(512, 2)
k_gemm2(const float* __restrict__ att_s, const float* __restrict__ att_d) {
    extern __shared__ __align__(16) char smem[];
    __half* sA = (__half*)smem;
    __half* sB = (__half*)(smem + 33792);
    float*  sC = (float*)smem;                 // aliases sA (dead after mainloop)
    float*  attS = (float*)(smem + 70656);
    float*  attD = attS + HID;
    int t = threadIdx.x;
    int w = t >> 5;
    int wm = w >> 2, wn = w & 3;
    int m0 = blockIdx.x * 64;

    // stage A: 64 rows x 256 fp16
    for (int i = t; i < 2048; i += 512) {
        int r = i >> 5, q = i & 31;
        uint4 v = make_uint4(0, 0, 0, 0);
        if (m0 + r < NNODES) v = *(const uint4*)(g_h1eh + (size_t)(m0 + r) * C1 + q * 8);
        *(uint4*)(sA + r * 264 + q * 8) = v;
    }
    // stage B: all of W2, 256 rows x 64 fp16
    for (int i = t; i < 2048; i += 512) {
        int r = i >> 3, q = i & 7;
        *(uint4*)(sB + r * 72 + q * 8) = *(const uint4*)(g_w2h + (size_t)r * HID + q * 8);
    }
    __syncthreads();

    wmma::fragment<wmma::accumulator, 16, 16, 16, float> c;
    wmma::fill_fragment(c, 0.f);

#pragma unroll
    for (int kk = 0; kk < 16; kk++) {
        wmma::fragment<wmma::matrix_a, 16, 16, 16, __half, wmma::row_major> af;
        wmma::load_matrix_sync(af, sA + wm * 16 * 264 + kk * 16, 264);
        wmma::fragment<wmma::matrix_b, 16, 16, 16, __half, wmma::row_major> bf;
        wmma::load_matrix_sync(bf, sB + kk * 16 * 72 + wn * 16, 72);
        wmma::mma_sync(c, af, bf, c);
    }

    __syncthreads();                 // sA/sB dead
    if (t < HID) attS[t] = att_s[t];
    else if (t < 2 * HID) attD[t - HID] = att_d[t - HID];
    wmma::store_matrix_sync(sC + (wm * 16) * 68 + wn * 16, c, 68, wmma::mem_row_major);
    __syncthreads();

    // each thread: 4 rows x 2 cols
    int r0 = t >> 5, q = t & 31, c0 = q * 2;
#pragma unroll
    for (int k = 0; k < 4; k++) {
        int r = r0 + k * 16;
        int n = m0 + r;
        const float* src = sC + r * 68 + c0;
        if (n < NNODES)
            *(__half2*)(g_h2h + (size_t)n * HID + c0) = __floats2half2_rn(src[0], src[1]);
        float ps = src[0] * attS[c0] + src[1] * attS[c0 + 1];
        float pd = src[0] * attD[c0] + src[1] * attD[c0 + 1];
#pragma unroll
        for (int s = 1; s <= 16; s <<= 1) {
            ps += __shfl_xor_sync(0xffffffffu, ps, s);
            pd += __shfl_xor_sync(0xffffffffu, pd, s);
        }
        if (q == 0 && n < NNODES) {
            g_as2[n] = ps;
            g_ad2[n] = pd;
        }
    }
}

// ---------------- layer 2 aggregation + bias/ELU + MLP head -----------------
__global__ void k_agg2(const float* __restrict__ b2,
                       const float* __restrict__ Wm1, const float* __restrict__ bm1,
                       const float* __restrict__ Wm2, const float* __restrict__ bm2,
                       float* __restrict__ out) {
    __shared__ float sh[4][HID];
    int wid = threadIdx.x >> 5, l = threadIdx.x & 31;
    int d = blockIdx.x * 4 + wid;
    if (d >= NNODES) return;
    int grp = l >> 3, cl = l & 7;
    int ch = 8 * cl;

    float adst = g_ad2[d];
    float den = 0.f;
    float a[8] = {0.f, 0.f, 0.f, 0.f, 0.f, 0.f, 0.f, 0.f};
    if (grp == 0) {                        // self-loop counted once
        float w = __expf(lrelu(g_as2[d] + adst));
        den = w;
        uint4 raw = *(const uint4*)(g_h2h + (size_t)d * HID + ch);
        const __half2* hp = (const __half2*)&raw;
#pragma unroll
        for (int i = 0; i < 4; i++) {
            float2 v = __half22float2(hp[i]);
            a[2 * i]     = w * v.x;
            a[2 * i + 1] = w * v.y;
        }
    }

    int beg = g_rowptr[d], end = g_rowptr[d + 1];
#pragma unroll 2
    for (int j = beg + grp; j < end; j += 4) {
        int s = g_col[j];
        float ww = __expf(lrelu(g_as2[s] + adst));
        den += ww;
        uint4 raw = *(const uint4*)(g_h2h + (size_t)s * HID + ch);
        const __half2* hp = (const __half2*)&raw;
#pragma unroll
        for (int i = 0; i < 4; i++) {
            float2 v = __half22float2(hp[i]);
            a[2 * i]     = fmaf(ww, v.x, a[2 * i]);
            a[2 * i + 1] = fmaf(ww, v.y, a[2 * i + 1]);
        }
    }

#pragma unroll
    for (int m = 8; m <= 16; m <<= 1) {
        den += __shfl_xor_sync(0xffffffffu, den, m);
#pragma unroll
        for (int i = 0; i < 8; i++) a[i] += __shfl_xor_sync(0xffffffffu, a[i], m);
    }

    float inv = 1.f / den;
    if (grp == 0) {
#pragma unroll
        for (int i = 0; i < 8; i++) {
            float hv = a[i] * inv + b2[ch + i];
            hv = hv > 0.f ? hv : expm1f(hv);
            sh[wid][ch + i] = hv;
        }
    }
    __syncwarp();

    float acc = bm1[l];
#pragma unroll
    for (int k = 0; k < HID; k++) acc = fmaf(sh[wid][k], Wm1[k * 32 + l], acc);
    float hid = acc > 0.f ? acc : 0.f;

    float p0 = hid * Wm2[l * 2];
    float p1 = hid * Wm2[l * 2 + 1];
#pragma unroll
    for (int s = 16; s >= 1; s >>= 1) {
        p0 += __shfl_xor_sync(0xffffffffu, p0, s);
        p1 += __shfl_xor_sync(0xffffffffu, p1, s);
    }
    if (l == 0) {
        out[d * 2]     = p0 + bm2[0];
        out[d * 2 + 1] = p1 + bm2[1];
    }
}

// ---------------- launch ----------------------------------------------------
extern "C" void kernel_launch(void* const* d_in, const int* in_sizes, int n_in,
                              void* d_out, int out_size) {
    const float* x   = (const float*)d_in[0];
    const int*   ei  = (const int*)  d_in[1];   // [2, E] int32: row0=src, row1=dst
    const float* W1  = (const float*)d_in[2];
    const float* as1 = (const float*)d_in[3];
    const float* ad1 = (const float*)d_in[4];
    const float* b1  = (const float*)d_in[5];
    const float* W2  = (const float*)d_in[6];
    const float* as2 = (const float*)d_in[7];
    const float* ad2 = (const float*)d_in[8];
    const float* b2  = (const float*)d_in[9];
    const float* Wm1 = (const float*)d_in[10];
    const float* bm1 = (const float*)d_in[11];
    const float* Wm2 = (const float*)d_in[12];
    const float* bm2 = (const float*)d_in[13];
    float* out = (float*)d_out;

    const int* src = ei;
    const int* dst = ei + NEDGES;

    cudaFuncSetAttribute(k_gemm1, cudaFuncAttributeMaxDynamicSharedMemorySize, SZ1);
    cudaFuncSetAttribute(k_gemm2, cudaFuncAttributeMaxDynamicSharedMemorySize, SZ2);

    k_cvtw   <<<(INF * C1 + 255) / 256, 256>>>(W1, W2);          // 0
    k_hist   <<<(NEDGES + 255) / 256, 256>>>(dst);               // 1
    k_scan1  <<<49, 1024>>>();                                   // 2
    k_gemm1  <<<(NNODES + 63) / 64, 512, SZ1>>>(x, as1, ad1);    // 3 <- profiled
    k_scan23 <<<49, 1024>>>();                                   // 4
    k_scatter<<<(NEDGES + 255) / 256, 256>>>(src, dst);          // 5
    k_agg1   <<<(NNODES + 3) / 4, 128>>>(b1);                    // 6
    k_gemm2  <<<(NNODES + 63) / 64, 512, SZ2>>>(as2, ad2);       // 7
    k_agg2   <<<(NNODES + 3) / 4, 128>>>(b2, Wm1, bm1, Wm2, bm2, out);  // 8
}

// round 14
// speedup vs baseline: 1.9652x; 1.0230x over previous
#include <cuda_runtime.h>
#include <cuda_fp16.h>
#include <mma.h>
#include <math.h>

using namespace nvcuda;

#define NNODES 50000
#define NEDGES 800000
#define INF    128
#define HID    64
#define HEADS  4
#define C1     256   // HEADS*HID
#define NEG    0.2f

// ---------------- scratch (device globals; no runtime allocation) ----------
__device__ __half g_w1h [INF * C1];     // W1 fp16
__device__ __half g_w2h [C1 * HID];     // W2 fp16
__device__ __half g_h1h [NNODES * C1];  // layer1 pre-attention features (fp16)
__device__ __half g_h1eh[NNODES * C1];  // layer1 output (post bias+ELU), fp16
__device__ float  g_as1[NNODES * HEADS];
__device__ float  g_ad1[NNODES * HEADS];
__device__ __half g_h2h[NNODES * HID];  // layer2 pre-attention features (fp16)
__device__ float  g_as2[NNODES];
__device__ float  g_ad2[NNODES];
__device__ int    g_deg   [NNODES];
__device__ int    g_rowptr[NNODES + 1];
__device__ int    g_cursor[NNODES];
__device__ int    g_col   [NEDGES];
__device__ int    g_bsum  [64];

__device__ __forceinline__ float lrelu(float v) { return v > 0.f ? v : NEG * v; }

// ---------------- fp16 weight conversion + degree histogram (fused) ---------
__global__ void k_cvthist(const float* __restrict__ W1, const float* __restrict__ W2,
                          const int* __restrict__ dst) {
    int i = blockIdx.x * blockDim.x + threadIdx.x;
    if (i < INF * C1)  g_w1h[i] = __float2half_rn(W1[i]);
    if (i < C1 * HID)  g_w2h[i] = __float2half_rn(W2[i]);
    if (i < NEDGES)    atomicAdd(&g_deg[dst[i]], 1);
}

// ---------------- CSR construction ------------------------------------------
__global__ void k_scan1() {
    __shared__ int sh[1024];
    int tid = threadIdx.x;
    int i = blockIdx.x * 1024 + tid;
    int v = (i < NNODES) ? g_deg[i] : 0;
    sh[tid] = v;
    __syncthreads();
    for (int s = 1; s < 1024; s <<= 1) {
        int t = (tid >= s) ? sh[tid - s] : 0;
        __syncthreads();
        sh[tid] += t;
        __syncthreads();
    }
    if (i < NNODES) g_rowptr[i] = sh[tid] - v;
    if (tid == 1023) g_bsum[blockIdx.x] = sh[1023];
}

// apply per-block offset, init cursor, zero g_deg for next replay
__global__ void k_scan23() {
    __shared__ int soff;
    int tid = threadIdx.x;
    int bid = blockIdx.x;
    if (tid < 32) {
        int v = 0;
        if (tid < bid && tid < 49) v += g_bsum[tid];
        int t2 = tid + 32;
        if (t2 < bid && t2 < 49) v += g_bsum[t2];
#pragma unroll
        for (int s = 16; s >= 1; s >>= 1) v += __shfl_xor_sync(0xffffffffu, v, s);
        if (tid == 0) soff = v;
    }
    __syncthreads();
    int i = bid * 1024 + tid;
    if (i < NNODES) {
        int r = g_rowptr[i] + soff;
        g_rowptr[i] = r;
        g_cursor[i] = r;
        g_deg[i] = 0;
    }
    if (i == 0) g_rowptr[NNODES] = NEDGES;
}

__global__ void k_scatter(const int* __restrict__ src, const int* __restrict__ dst) {
    int i = blockIdx.x * blockDim.x + threadIdx.x;
    if (i < NEDGES) {
        int p = atomicAdd(&g_cursor[dst[i]], 1);
        g_col[p] = src[i];
    }
}

// ---------------- layer 1 GEMM via wmma: 64 nodes x 256 ch per block --------
// 512 threads = 16 warps as 2m x 8n; warp tile 32 x 32 (2x2 accum frags);
// per kk: 2 af + 2 bf tile loads (bf reused across m) -> -20% mainloop LDS.
// Single-phase epilogue; attention vectors staged TRANSPOSED (conflict-free).
// smem: mainloop [0,17408) sA | [17408,84992) sB ; epilogue [0,66560) sC
//       [84992,86016) attTs | [86016,87040) attTd
#define SZ1 87040
__global__ void __launch_bounds__(512, 2)
k_gemm1(const float* __restrict__ x,
        const float* __restrict__ att_s, const float* __restrict__ att_d) {
    extern __shared__ __align__(16) char smem[];
    __half* sA = (__half*)smem;
    __half* sB = (__half*)(smem + 17408);
    float*  sC = (float*)smem;                 // aliases sA+sB (dead after mainloop)
    float*  attTs = (float*)(smem + 84992);    // attTs[i*32+q] = att_s[q*8+i]
    float*  attTd = (float*)(smem + 86016);
    int t = threadIdx.x;
    int w = t >> 5;
    int wmh = w & 1, wng = w >> 1;             // m-half 0..1, n-group 0..7
    int m0 = blockIdx.x * 64;

    // stage transposed attention vectors (own region; no aliasing)
    if (t < C1)           attTs[(t & 7) * 32 + (t >> 3)] = att_s[t];
    else if (t < 2 * C1)  { int u = t - C1; attTd[(u & 7) * 32 + (u >> 3)] = att_d[u]; }

    // stage A with fused fp32->fp16: 64 rows x 128 ch
    for (int i = t; i < 1024; i += 512) {
        int r = i >> 4, q = i & 15;
        int n = m0 + r;
        uint4 st = make_uint4(0, 0, 0, 0);
        if (n < NNODES) {
            const float4* xp = (const float4*)(x + (size_t)n * INF + q * 8);
            float4 v0 = xp[0], v1 = xp[1];
            __half2* p = (__half2*)&st;
            p[0] = __floats2half2_rn(v0.x, v0.y);
            p[1] = __floats2half2_rn(v0.z, v0.w);
            p[2] = __floats2half2_rn(v1.x, v1.y);
            p[3] = __floats2half2_rn(v1.z, v1.w);
        }
        *(uint4*)(sA + r * 136 + q * 8) = st;
    }
    // stage B: all of W1, 128 rows x 256 fp16
    for (int i = t; i < 4096; i += 512) {
        int r = i >> 5, q = i & 31;
        *(uint4*)(sB + r * 264 + q * 8) = *(const uint4*)(g_w1h + (size_t)r * C1 + q * 8);
    }
    __syncthreads();

    wmma::fragment<wmma::accumulator, 16, 16, 16, float> c[2][2];
#pragma unroll
    for (int i = 0; i < 2; i++)
#pragma unroll
        for (int j = 0; j < 2; j++) wmma::fill_fragment(c[i][j], 0.f);

#pragma unroll
    for (int kk = 0; kk < 8; kk++) {
        wmma::fragment<wmma::matrix_a, 16, 16, 16, __half, wmma::row_major> af[2];
#pragma unroll
        for (int i = 0; i < 2; i++)
            wmma::load_matrix_sync(af[i], sA + (wmh * 2 + i) * 16 * 136 + kk * 16, 136);
#pragma unroll
        for (int j = 0; j < 2; j++) {
            wmma::fragment<wmma::matrix_b, 16, 16, 16, __half, wmma::row_major> bf;
            wmma::load_matrix_sync(bf, sB + kk * 16 * 264 + (wng * 2 + j) * 16, 264);
            wmma::mma_sync(c[0][j], af[0], bf, c[0][j]);
            wmma::mma_sync(c[1][j], af[1], bf, c[1][j]);
        }
    }

    __syncthreads();                 // sA/sB dead; sC live
#pragma unroll
    for (int i = 0; i < 2; i++)
#pragma unroll
        for (int j = 0; j < 2; j++)
            wmma::store_matrix_sync(sC + ((wmh * 2 + i) * 16) * 260 + (wng * 2 + j) * 16,
                                    c[i][j], 260, wmma::mem_row_major);
    __syncthreads();

    // each thread: 4 rows x 8 cols; fp16 store + fused attention dots
    int r0 = t >> 5, q = t & 31, c0 = q * 8;
#pragma unroll
    for (int k = 0; k < 4; k++) {
        int r = r0 + k * 16;
        int n = m0 + r;
        const float* src = sC + r * 260 + c0;
        if (n < NNODES) {
            uint4 st;
            __half2* p = (__half2*)&st;
            p[0] = __floats2half2_rn(src[0], src[1]);
            p[1] = __floats2half2_rn(src[2], src[3]);
            p[2] = __floats2half2_rn(src[4], src[5]);
            p[3] = __floats2half2_rn(src[6], src[7]);
            *(uint4*)(g_h1h + (size_t)n * C1 + c0) = st;
        }
        float ps = 0.f, pd = 0.f;
#pragma unroll
        for (int i = 0; i < 8; i++) {
            float v = src[i];
            ps = fmaf(v, attTs[i * 32 + q], ps);
            pd = fmaf(v, attTd[i * 32 + q], pd);
        }
#pragma unroll
        for (int s = 1; s <= 4; s <<= 1) {
            ps += __shfl_xor_sync(0xffffffffu, ps, s);
            pd += __shfl_xor_sync(0xffffffffu, pd, s);
        }
        if ((q & 7) == 0 && n < NNODES) {
            int h = q >> 3;
            g_as1[n * HEADS + h] = ps;
            g_ad1[n * HEADS + h] = pd;
        }
    }
}

// ---------------- layer 1: warp-per-destination softmax aggregation ---------
// scores |e| <~ 10 so exp() cannot overflow fp32; max-shift unnecessary.
__global__ void k_agg1(const float* __restrict__ b1) {
    int wid = threadIdx.x >> 5, l = threadIdx.x & 31;
    int d = blockIdx.x * 4 + wid;
    if (d >= NNODES) return;
    int h = l >> 3;
    int ch = 8 * l;

    float adst = g_ad1[d * HEADS + h];
    float w = __expf(lrelu(g_as1[d * HEADS + h] + adst));  // self-loop
    float den = w;
    float a[8];
    {
        uint4 raw = *(const uint4*)(g_h1h + (size_t)d * C1 + ch);
        const __half2* hp = (const __half2*)&raw;
#pragma unroll
        for (int i = 0; i < 4; i++) {
            float2 v = __half22float2(hp[i]);
            a[2 * i]     = w * v.x;
            a[2 * i + 1] = w * v.y;
        }
    }

    int beg = g_rowptr[d], end = g_rowptr[d + 1];
#pragma unroll 4
    for (int j = beg; j < end; j++) {
        int s = g_col[j];
        float ww = __expf(lrelu(g_as1[s * HEADS + h] + adst));
        den += ww;
        uint4 raw = *(const uint4*)(g_h1h + (size_t)s * C1 + ch);
        const __half2* hp = (const __half2*)&raw;
#pragma unroll
        for (int i = 0; i < 4; i++) {
            float2 v = __half22float2(hp[i]);
            a[2 * i]     = fmaf(ww, v.x, a[2 * i]);
            a[2 * i + 1] = fmaf(ww, v.y, a[2 * i + 1]);
        }
    }
    float inv = 1.f / den;
    float4 b0 = *(const float4*)(b1 + ch);
    float4 b4 = *(const float4*)(b1 + ch + 4);
    float o[8];
    o[0] = a[0] * inv + b0.x; o[1] = a[1] * inv + b0.y;
    o[2] = a[2] * inv + b0.z; o[3] = a[3] * inv + b0.w;
    o[4] = a[4] * inv + b4.x; o[5] = a[5] * inv + b4.y;
    o[6] = a[6] * inv + b4.z; o[7] = a[7] * inv + b4.w;
#pragma unroll
    for (int i = 0; i < 8; i++) o[i] = o[i] > 0.f ? o[i] : expm1f(o[i]);
    uint4 st;
    __half2* sp = (__half2*)&st;
    sp[0] = __floats2half2_rn(o[0], o[1]);
    sp[1] = __floats2half2_rn(o[2], o[3]);
    sp[2] = __floats2half2_rn(o[4], o[5]);
    sp[3] = __floats2half2_rn(o[6], o[7]);
    *(uint4*)(g_h1eh + (size_t)d * C1 + ch) = st;
}

// ---------------- layer 2 GEMM via wmma: 64 nodes x 64 ch per block ---------
// 512 threads = 16 warps (4m x 4n); warp tile 16 x 16 (1 accum frag).
// layout: mainloop [0,33792) sA | [33792,70656) sB
//         epilogue [0,17408) sC | [70656,70912) attTs | [70912,71168) attTd
#define SZ2 71168
__global__ void __launch_bounds__(512, 2)
k_gemm2(const float* __restrict__ att_s, const float* __restrict__ att_d) {
    extern __shared__ __align__(16) char smem[];
    __half* sA = (__half*)smem;
    __half* sB = (__half*)(smem + 33792);
    float*  sC = (float*)smem;                 // aliases sA (dead after mainloop)
    float*  attTs = (float*)(smem + 70656);    // attTs[i*32+q] = att_s[q*2+i]
    float*  attTd = (float*)(smem + 70912);
    int t = threadIdx.x;
    int w = t >> 5;
    int wm = w >> 2, wn = w & 3;
    int m0 = blockIdx.x * 64;

    if (t < HID)            attTs[(t & 1) * 32 + (t >> 1)] = att_s[t];
    else if (t < 2 * HID)   { int u = t - HID; attTd[(u & 1) * 32 + (u >> 1)] = att_d[u]; }

    // stage A: 64 rows x 256 fp16
    for (int i = t; i < 2048; i += 512) {
        int r = i >> 5, q = i & 31;
        uint4 v = make_uint4(0, 0, 0, 0);
        if (m0 + r < NNODES) v = *(const uint4*)(g_h1eh + (size_t)(m0 + r) * C1 + q * 8);
        *(uint4*)(sA + r * 264 + q * 8) = v;
    }
    // stage B: all of W2, 256 rows x 64 fp16
    for (int i = t; i < 2048; i += 512) {
        int r = i >> 3, q = i & 7;
        *(uint4*)(sB + r * 72 + q * 8) = *(const uint4*)(g_w2h + (size_t)r * HID + q * 8);
    }
    __syncthreads();

    wmma::fragment<wmma::accumulator, 16, 16, 16, float> c;
    wmma::fill_fragment(c, 0.f);

#pragma unroll
    for (int kk = 0; kk < 16; kk++) {
        wmma::fragment<wmma::matrix_a, 16, 16, 16, __half, wmma::row_major> af;
        wmma::load_matrix_sync(af, sA + wm * 16 * 264 + kk * 16, 264);
        wmma::fragment<wmma::matrix_b, 16, 16, 16, __half, wmma::row_major> bf;
        wmma::load_matrix_sync(bf, sB + kk * 16 * 72 + wn * 16, 72);
        wmma::mma_sync(c, af, bf, c);
    }

    __syncthreads();                 // sA/sB dead
    wmma::store_matrix_sync(sC + (wm * 16) * 68 + wn * 16, c, 68, wmma::mem_row_major);
    __syncthreads();

    // each thread: 4 rows x 2 cols
    int r0 = t >> 5, q = t & 31, c0 = q * 2;
#pragma unroll
    for (int k = 0; k < 4; k++) {
        int r = r0 + k * 16;
        int n = m0 + r;
        const float* src = sC + r * 68 + c0;
        if (n < NNODES)
            *(__half2*)(g_h2h + (size_t)n * HID + c0) = __floats2half2_rn(src[0], src[1]);
        float ps = src[0] * attTs[q] + src[1] * attTs[32 + q];
        float pd = src[0] * attTd[q] + src[1] * attTd[32 + q];
#pragma unroll
        for (int s = 1; s <= 16; s <<= 1) {
            ps += __shfl_xor_sync(0xffffffffu, ps, s);
            pd += __shfl_xor_sync(0xffffffffu, pd, s);
        }
        if (q == 0 && n < NNODES) {
            g_as2[n] = ps;
            g_ad2[n] = pd;
        }
    }
}

// ---------------- layer 2 aggregation + bias/ELU + MLP head -----------------
__global__ void k_agg2(const float* __restrict__ b2,
                       const float* __restrict__ Wm1, const float* __restrict__ bm1,
                       const float* __restrict__ Wm2, const float* __restrict__ bm2,
                       float* __restrict__ out) {
    __shared__ float sh[4][HID];
    int wid = threadIdx.x >> 5, l = threadIdx.x & 31;
    int d = blockIdx.x * 4 + wid;
    if (d >= NNODES) return;
    int grp = l >> 3, cl = l & 7;
    int ch = 8 * cl;

    float adst = g_ad2[d];
    float den = 0.f;
    float a[8] = {0.f, 0.f, 0.f, 0.f, 0.f, 0.f, 0.f, 0.f};
    if (grp == 0) {                        // self-loop counted once
        float w = __expf(lrelu(g_as2[d] + adst));
        den = w;
        uint4 raw = *(const uint4*)(g_h2h + (size_t)d * HID + ch);
        const __half2* hp = (const __half2*)&raw;
#pragma unroll
        for (int i = 0; i < 4; i++) {
            float2 v = __half22float2(hp[i]);
            a[2 * i]     = w * v.x;
            a[2 * i + 1] = w * v.y;
        }
    }

    int beg = g_rowptr[d], end = g_rowptr[d + 1];
#pragma unroll 2
    for (int j = beg + grp; j < end; j += 4) {
        int s = g_col[j];
        float ww = __expf(lrelu(g_as2[s] + adst));
        den += ww;
        uint4 raw = *(const uint4*)(g_h2h + (size_t)s * HID + ch);
        const __half2* hp = (const __half2*)&raw;
#pragma unroll
        for (int i = 0; i < 4; i++) {
            float2 v = __half22float2(hp[i]);
            a[2 * i]     = fmaf(ww, v.x, a[2 * i]);
            a[2 * i + 1] = fmaf(ww, v.y, a[2 * i + 1]);
        }
    }

#pragma unroll
    for (int m = 8; m <= 16; m <<= 1) {
        den += __shfl_xor_sync(0xffffffffu, den, m);
#pragma unroll
        for (int i = 0; i < 8; i++) a[i] += __shfl_xor_sync(0xffffffffu, a[i], m);
    }

    float inv = 1.f / den;
    if (grp == 0) {
#pragma unroll
        for (int i = 0; i < 8; i++) {
            float hv = a[i] * inv + b2[ch + i];
            hv = hv > 0.f ? hv : expm1f(hv);
            sh[wid][ch + i] = hv;
        }
    }
    __syncwarp();

    float acc = bm1[l];
#pragma unroll
    for (int k = 0; k < HID; k++) acc = fmaf(sh[wid][k], Wm1[k * 32 + l], acc);
    float hid = acc > 0.f ? acc : 0.f;

    float p0 = hid * Wm2[l * 2];
    float p1 = hid * Wm2[l * 2 + 1];
#pragma unroll
    for (int s = 16; s >= 1; s >>= 1) {
        p0 += __shfl_xor_sync(0xffffffffu, p0, s);
        p1 += __shfl_xor_sync(0xffffffffu, p1, s);
    }
    if (l == 0) {
        out[d * 2]     = p0 + bm2[0];
        out[d * 2 + 1] = p1 + bm2[1];
    }
}

// ---------------- launch ----------------------------------------------------
extern "C" void kernel_launch(void* const* d_in, const int* in_sizes, int n_in,
                              void* d_out, int out_size) {
    const float* x   = (const float*)d_in[0];
    const int*   ei  = (const int*)  d_in[1];   // [2, E] int32: row0=src, row1=dst
    const float* W1  = (const float*)d_in[2];
    const float* as1 = (const float*)d_in[3];
    const float* ad1 = (const float*)d_in[4];
    const float* b1  = (const float*)d_in[5];
    const float* W2  = (const float*)d_in[6];
    const float* as2 = (const float*)d_in[7];
    const float* ad2 = (const float*)d_in[8];
    const float* b2  = (const float*)d_in[9];
    const float* Wm1 = (const float*)d_in[10];
    const float* bm1 = (const float*)d_in[11];
    const float* Wm2 = (const float*)d_in[12];
    const float* bm2 = (const float*)d_in[13];
    float* out = (float*)d_out;

    const int* src = ei;
    const int* dst = ei + NEDGES;

    cudaFuncSetAttribute(k_gemm1, cudaFuncAttributeMaxDynamicSharedMemorySize, SZ1);
    cudaFuncSetAttribute(k_gemm2, cudaFuncAttributeMaxDynamicSharedMemorySize, SZ2);

    k_cvthist<<<(NEDGES + 255) / 256, 256>>>(W1, W2, dst);       // 0
    k_scan1  <<<49, 1024>>>();                                   // 1
    k_scan23 <<<49, 1024>>>();                                   // 2
    k_gemm1  <<<(NNODES + 63) / 64, 512, SZ1>>>(x, as1, ad1);    // 3 <- profiled
    k_scatter<<<(NEDGES + 255) / 256, 256>>>(src, dst);          // 4
    k_agg1   <<<(NNODES + 3) / 4, 128>>>(b1);                    // 5
    k_gemm2  <<<(NNODES + 63) / 64, 512, SZ2>>>(as2, ad2);       // 6
    k_agg2   <<<(NNODES + 3) / 4, 128>>>(b2, Wm1, bm1, Wm2, bm2, out);  // 7
}